// round 9
// baseline (speedup 1.0000x reference)
#include <cuda_runtime.h>
#include <cuda_bf16.h>
#include <math.h>
#include <stdint.h>

#define BB 16
#define NN 1024
#define FIN 64
#define HH 256
#define NEGV (-9e15f)
#define LALPHA 0.2f

typedef __nv_bfloat16 bf16;

// ---------------- scratch (device globals: no allocation allowed) ----------
__device__ __align__(256) bf16 g_ahi[BB * NN * HH];
__device__ __align__(256) bf16 g_alo[BB * NN * HH];
__device__ __align__(256) bf16 g_chi[BB * NN * HH];
__device__ __align__(256) bf16 g_clo[BB * NN * HH];
__device__ __align__(256) bf16 g_bhi[BB * NN * HH];
__device__ __align__(256) bf16 g_blo[BB * NN * HH];
__device__ __align__(256) bf16 g_whi[HH * HH];
__device__ __align__(256) bf16 g_wlo[HH * HH];
__device__ __align__(256) uint32_t g_adjbits[BB * NN * (NN / 32)];
__device__ __align__(256) float g_s1[BB * NN];
__device__ __align__(256) float g_s2[BB * NN];
__device__ __align__(256) float g_m[BB * NN];
__device__ __align__(256) float g_linv[BB * NN];
__device__ __align__(256) float g_sum[BB * HH];
__device__ __align__(256) float g_max[BB * HH];

// ---------------- helpers --------------------------------------------------
__device__ __forceinline__ uint32_t swz(uint32_t o) {
    return o ^ ((o >> 3) & 0x70);
}
__device__ __forceinline__ uint32_t su32(const void* p) {
    uint32_t a;
    asm("{ .reg .u64 t; cvta.to.shared.u64 t, %1; cvt.u32.u64 %0, t; }"
        : "=r"(a) : "l"(p));
    return a;
}
#define CP16(d, s)                                                            \
    asm volatile("cp.async.cg.shared.global [%0], [%1], 16;" ::"r"(d), "l"(s))
#define CPCOMMIT() asm volatile("cp.async.commit_group;" ::: "memory")
#define CPWAIT0() asm volatile("cp.async.wait_group 0;" ::: "memory")

__device__ __forceinline__ void ldsm4(uint32_t addr, uint32_t* r) {
    asm volatile("ldmatrix.sync.aligned.m8n8.x4.shared.b16 {%0,%1,%2,%3}, [%4];"
                 : "=r"(r[0]), "=r"(r[1]), "=r"(r[2]), "=r"(r[3]) : "r"(addr));
}
__device__ __forceinline__ void ldsm4t(uint32_t addr, uint32_t* r) {
    asm volatile("ldmatrix.sync.aligned.m8n8.x4.trans.shared.b16 {%0,%1,%2,%3}, [%4];"
                 : "=r"(r[0]), "=r"(r[1]), "=r"(r[2]), "=r"(r[3]) : "r"(addr));
}
__device__ __forceinline__ void mma16816(float* c, const uint32_t* a,
                                         const uint32_t* b) {
    asm volatile(
        "mma.sync.aligned.m16n8k16.row.col.f32.bf16.bf16.f32 "
        "{%0,%1,%2,%3}, {%4,%5,%6,%7}, {%8,%9}, {%0,%1,%2,%3};"
        : "+f"(c[0]), "+f"(c[1]), "+f"(c[2]), "+f"(c[3])
        : "r"(a[0]), "r"(a[1]), "r"(a[2]), "r"(a[3]), "r"(b[0]), "r"(b[1]));
}

// warp mma over one 64-k chunk, 3-pass hi/lo split.
// ILP-friendly: each pass issues 16 INDEPENDENT MMAs so same-accumulator
// RAW pairs are >=16 instructions apart (round-8 latency fix).
__device__ __forceinline__ void mma_chunk(uint32_t aHi, uint32_t aLo,
                                          uint32_t bHi, uint32_t bLo,
                                          int wm, int lane,
                                          float acc[2][8][4])
{
    int rA = lane & 15;
    int cA = (lane >> 4) * 16;
#pragma unroll
    for (int ks = 0; ks < 4; ks++) {
        uint32_t ah[2][4], al[2][4], bb[4][4];
#pragma unroll
        for (int h = 0; h < 2; h++) {
            uint32_t off = swz((uint32_t)(wm * 32 + h * 16 + rA) * 128 +
                               ks * 32 + cA);
            ldsm4(aHi + off, ah[h]);
            ldsm4(aLo + off, al[h]);
        }
#pragma unroll
        for (int t = 0; t < 4; t++) {
            uint32_t off = swz((uint32_t)(ks * 16 + rA) * 128 + t * 32 + cA);
            ldsm4t(bHi + off, bb[t]);
        }
        // pass 1: hi*hi (16 independent MMAs)
#pragma unroll
        for (int h = 0; h < 2; h++)
#pragma unroll
            for (int t = 0; t < 4; t++) {
                mma16816(acc[h][2 * t], ah[h], bb[t]);
                mma16816(acc[h][2 * t + 1], ah[h], bb[t] + 2);
            }
        // pass 2: lo*hi (16 independent MMAs)
#pragma unroll
        for (int h = 0; h < 2; h++)
#pragma unroll
            for (int t = 0; t < 4; t++) {
                mma16816(acc[h][2 * t], al[h], bb[t]);
                mma16816(acc[h][2 * t + 1], al[h], bb[t] + 2);
            }
        // pass 3: hi*lo (16 independent MMAs)
#pragma unroll
        for (int t = 0; t < 4; t++) {
            uint32_t off = swz((uint32_t)(ks * 16 + rA) * 128 + t * 32 + cA);
            ldsm4t(bLo + off, bb[t]);
        }
#pragma unroll
        for (int h = 0; h < 2; h++)
#pragma unroll
            for (int t = 0; t < 4; t++) {
                mma16816(acc[h][2 * t], ah[h], bb[t]);
                mma16816(acc[h][2 * t + 1], ah[h], bb[t] + 2);
            }
    }
}

__device__ __forceinline__ void split2(float v0, float v1, uint32_t& hw,
                                       uint32_t& lw) {
    __nv_bfloat162 h2 = __floats2bfloat162_rn(v0, v1);
    float r0 = v0 - __bfloat162float(h2.x);
    float r1 = v1 - __bfloat162float(h2.y);
    __nv_bfloat162 l2 = __floats2bfloat162_rn(r0, r1);
    hw = *(uint32_t*)&h2;
    lw = *(uint32_t*)&l2;
}

// ---------------- prep kernels ---------------------------------------------
__global__ void packbits_kernel(const float* __restrict__ adj,
                                uint32_t* __restrict__ bits)
{
    int row = (blockIdx.x * blockDim.x + threadIdx.x) >> 5;
    int lane = threadIdx.x & 31;
    if (row >= BB * NN) return;
    const float* ar = adj + (size_t)row * NN;
    uint32_t myword = 0;
#pragma unroll
    for (int wd = 0; wd < 32; wd++) {
        uint32_t v = __ballot_sync(0xffffffffu, ar[wd * 32 + lane] > 0.f);
        if (lane == wd) myword = v;
    }
    bits[(size_t)row * 32 + lane] = myword;
}

__global__ void split_kernel(const float* __restrict__ X,
                             bf16* __restrict__ Xh, bf16* __restrict__ Xl,
                             int n4)
{
    int i = blockIdx.x * blockDim.x + threadIdx.x;
    if (i >= n4) return;
    float4 v = *(const float4*)(X + (size_t)i * 4);
    uint2 hw, lw;
    split2(v.x, v.y, hw.x, lw.x);
    split2(v.z, v.w, hw.y, lw.y);
    *(uint2*)(Xh + (size_t)i * 4) = hw;
    *(uint2*)(Xl + (size_t)i * 4) = lw;
}

// ---------------- pipelined GEMM: C = A[M,K] @ B[K,256] (+bias) ------------
__device__ __forceinline__ void gemm_load_chunk(
    uint32_t sb, int st, int tid, int m0, int k0,
    const bf16* Ah, const bf16* Al, const bf16* Bh, const bf16* Bl, int K)
{
    uint32_t s0 = sb + st * 98304;
#pragma unroll
    for (int i = tid; i < 1024; i += 512) {
        int r = i >> 3, cc = i & 7;
        size_t g = (size_t)(m0 + r) * K + k0 + cc * 8;
        uint32_t so = s0 + swz(r * 128 + cc * 16);
        CP16(so, Ah + g);
        CP16(so + 16384, Al + g);
    }
#pragma unroll
    for (int i = tid; i < 2048; i += 512) {
        int r = i >> 5, c32 = i & 31;
        int p = c32 >> 3, cc = c32 & 7;
        size_t g = (size_t)(k0 + r) * 256 + c32 * 8;
        uint32_t so = s0 + 32768 + p * 8192 + swz(r * 128 + cc * 16);
        CP16(so, Bh + g);
        CP16(so + 32768, Bl + g);
    }
}

__global__ void __launch_bounds__(512, 1) gemm_mma_kernel(
    const bf16* __restrict__ Ah, const bf16* __restrict__ Al,
    const bf16* __restrict__ Bh, const bf16* __restrict__ Bl,
    const float* __restrict__ bias, const float* __restrict__ a1,
    const float* __restrict__ a2, bf16* __restrict__ Chi,
    bf16* __restrict__ Clo, int K)
{
    extern __shared__ __align__(1024) char smem[];
    uint32_t sb = su32(smem);
    int tid = threadIdx.x, lane = tid & 31, w = tid >> 5;
    int wm = w >> 2, wn = w & 3;
    int m0 = blockIdx.x * 128;
    int nch = K >> 6;

    float acc[2][8][4];
#pragma unroll
    for (int h = 0; h < 2; h++)
#pragma unroll
        for (int t = 0; t < 8; t++)
#pragma unroll
            for (int e = 0; e < 4; e++) acc[h][t][e] = 0.f;

    gemm_load_chunk(sb, 0, tid, m0, 0, Ah, Al, Bh, Bl, K);
    CPCOMMIT();

    for (int c = 0; c < nch; c++) {
        int st = c & 1;
        CPWAIT0();
        __syncthreads();
        if (c + 1 < nch) {
            gemm_load_chunk(sb, st ^ 1, tid, m0, (c + 1) << 6, Ah, Al, Bh, Bl, K);
            CPCOMMIT();
        }
        mma_chunk(sb + st * 98304, sb + st * 98304 + 16384,
                  sb + st * 98304 + 32768 + wn * 8192,
                  sb + st * 98304 + 65536 + wn * 8192, wm, lane, acc);
    }

    // fused rowdot scratch
    float* s1s = (float*)(smem + 196608);
    float* s2s = s1s + 128;
    if (tid < 256) s1s[tid] = 0.f;
    __syncthreads();

    int grp = lane >> 2, qp = lane & 3;
#pragma unroll
    for (int h = 0; h < 2; h++) {
        int mA = m0 + wm * 32 + h * 16 + grp;
        float p1a = 0.f, p1b = 0.f, p2a = 0.f, p2b = 0.f;
#pragma unroll
        for (int t = 0; t < 8; t++) {
            int n = wn * 64 + t * 8 + qp * 2;
            float b0 = bias ? bias[n] : 0.f;
            float b1 = bias ? bias[n + 1] : 0.f;
            float v00 = acc[h][t][0] + b0, v01 = acc[h][t][1] + b1;
            float v10 = acc[h][t][2] + b0, v11 = acc[h][t][3] + b1;
            size_t o0 = (size_t)mA * HH + n;
            size_t o1 = (size_t)(mA + 8) * HH + n;
            uint32_t hw, lw;
            split2(v00, v01, hw, lw);
            *(uint32_t*)(Chi + o0) = hw;
            *(uint32_t*)(Clo + o0) = lw;
            split2(v10, v11, hw, lw);
            *(uint32_t*)(Chi + o1) = hw;
            *(uint32_t*)(Clo + o1) = lw;
            if (a1) {
                float a1v0 = a1[n], a1v1 = a1[n + 1];
                float a2v0 = a2[n], a2v1 = a2[n + 1];
                p1a += v00 * a1v0 + v01 * a1v1;
                p1b += v10 * a1v0 + v11 * a1v1;
                p2a += v00 * a2v0 + v01 * a2v1;
                p2b += v10 * a2v0 + v11 * a2v1;
            }
        }
        if (a1) {
            int lr = wm * 32 + h * 16 + grp;
            atomicAdd(&s1s[lr], p1a);
            atomicAdd(&s1s[lr + 8], p1b);
            atomicAdd(&s2s[lr], p2a);
            atomicAdd(&s2s[lr + 8], p2b);
        }
    }
    if (a1) {
        __syncthreads();
        if (tid < 128) {
            g_s1[m0 + tid] = s1s[tid];
            g_s2[m0 + tid] = s2s[tid];
        }
    }
}

// ---------------- softmax stats from bitmask -------------------------------
__global__ void stats_kernel(const uint32_t* __restrict__ bits)
{
    int warp_in = threadIdx.x >> 5;
    int lane = threadIdx.x & 31;
    int row = blockIdx.x * 8 + warp_in;
    int b = row >> 10;
    uint32_t w = bits[(size_t)row * 32 + lane];
    const float* s2b = g_s2 + (b << 10);
    float s1v = g_s1[row];
    float e[32];
    float m = -INFINITY;
#pragma unroll
    for (int jj = 0; jj < 32; jj++) {
        int j = jj * 32 + lane;
        uint32_t wj = __shfl_sync(0xffffffffu, w, jj);
        float t = s1v + s2b[j];
        t = (t >= 0.f) ? t : LALPHA * t;
        t = ((wj >> lane) & 1u) ? t : NEGV;
        e[jj] = t;
        m = fmaxf(m, t);
    }
#pragma unroll
    for (int off = 16; off; off >>= 1)
        m = fmaxf(m, __shfl_xor_sync(0xffffffffu, m, off));
    float l = 0.f;
#pragma unroll
    for (int jj = 0; jj < 32; jj++) l += __expf(e[jj] - m);
#pragma unroll
    for (int off = 16; off; off >>= 1)
        l += __shfl_xor_sync(0xffffffffu, l, off);
    if (lane == 0) { g_m[row] = m; g_linv[row] = 1.f / l; }
}

// ---------------- pipelined attention: out = relu(softmax(e) @ h) ----------
// smem: P stages 2x32768 @0 | H stages 2x65536 @65536 | s2/pool @196608.
__device__ __forceinline__ void attn_load_h(
    uint32_t sb, int st, int tid, int b, int j0,
    const bf16* Hh, const bf16* Hl)
{
    uint32_t s0 = sb + 65536 + st * 65536;
#pragma unroll
    for (int i = tid; i < 2048; i += 512) {
        int r = i >> 5, c32 = i & 31;
        int p = c32 >> 3, cc = c32 & 7;
        size_t g = (size_t)(b * NN + j0 + r) * 256 + c32 * 8;
        uint32_t so = s0 + p * 8192 + swz(r * 128 + cc * 16);
        CP16(so, Hh + g);
        CP16(so + 32768, Hl + g);
    }
}

__global__ void __launch_bounds__(512, 1) attn_mma_kernel(
    const uint32_t* __restrict__ bits, const bf16* __restrict__ Hh,
    const bf16* __restrict__ Hl, float* __restrict__ outF,
    bf16* __restrict__ Ohi, bf16* __restrict__ Olo)
{
    extern __shared__ __align__(1024) char smem[];
    uint32_t sb = su32(smem);
    int tid = threadIdx.x, lane = tid & 31, w = tid >> 5;
    int wm = w >> 2, wn = w & 3;
    int b = blockIdx.x >> 3;
    int i0 = (blockIdx.x & 7) << 7;

    float* s2s = (float*)(smem + 196608);

    int prow = tid >> 2;
    int pj = (tid & 3) * 16;
    int growi = b * NN + i0 + prow;
    float s1v = g_s1[growi];
    float mv = g_m[growi];
    const uint32_t* brow = bits + (size_t)growi * 32;

    for (int i = tid; i < NN; i += 512) s2s[i] = g_s2[b * NN + i];
    attn_load_h(sb, 0, tid, b, 0, Hh, Hl);
    CPCOMMIT();
    __syncthreads();

#define BUILD_P(cc, st)                                                        \
    do {                                                                       \
        int j0_ = (cc) << 6;                                                   \
        uint32_t word = brow[(j0_ >> 5) + (pj >> 5)];                          \
        int bitbase = pj & 31;                                                 \
        uint4 hw, lw, hw2, lw2;                                                \
        uint32_t* hp = (uint32_t*)&hw;                                         \
        uint32_t* lp = (uint32_t*)&lw;                                         \
        uint32_t* hp2 = (uint32_t*)&hw2;                                       \
        uint32_t* lp2 = (uint32_t*)&lw2;                                       \
        _Pragma("unroll") for (int q = 0; q < 8; q++) {                        \
            float e0 = s1v + s2s[j0_ + pj + 2 * q];                            \
            float e1 = s1v + s2s[j0_ + pj + 2 * q + 1];                        \
            e0 = (e0 >= 0.f) ? e0 : LALPHA * e0;                               \
            e1 = (e1 >= 0.f) ? e1 : LALPHA * e1;                               \
            float p0 = ((word >> (bitbase + 2 * q)) & 1u) ? __expf(e0 - mv) : 0.f; \
            float p1 = ((word >> (bitbase + 2 * q + 1)) & 1u) ? __expf(e1 - mv) : 0.f; \
            uint32_t hww, lww;                                                 \
            split2(p0, p1, hww, lww);                                          \
            if (q < 4) { hp[q] = hww; lp[q] = lww; }                           \
            else { hp2[q - 4] = hww; lp2[q - 4] = lww; }                       \
        }                                                                      \
        uint32_t o = (uint32_t)prow * 128 + pj * 2;                            \
        uint32_t so0 = swz(o), so1 = swz(o + 16);                              \
        char* pb = smem + (st) * 32768;                                        \
        *(uint4*)(pb + so0) = hw;                                              \
        *(uint4*)(pb + 16384 + so0) = lw;                                      \
        *(uint4*)(pb + so1) = hw2;                                             \
        *(uint4*)(pb + 16384 + so1) = lw2;                                     \
    } while (0)

    BUILD_P(0, 0);

    float acc[2][8][4];
#pragma unroll
    for (int h = 0; h < 2; h++)
#pragma unroll
        for (int t = 0; t < 8; t++)
#pragma unroll
            for (int e = 0; e < 4; e++) acc[h][t][e] = 0.f;

    for (int c = 0; c < 16; c++) {
        int st = c & 1;
        CPWAIT0();
        __syncthreads();
        if (c < 15) {
            attn_load_h(sb, st ^ 1, tid, b, (c + 1) << 6, Hh, Hl);
            CPCOMMIT();
            BUILD_P(c + 1, st ^ 1);
        }
        mma_chunk(sb + st * 32768, sb + st * 32768 + 16384,
                  sb + 65536 + st * 65536 + wn * 8192,
                  sb + 65536 + st * 65536 + 32768 + wn * 8192, wm, lane, acc);
    }
#undef BUILD_P

    // pooled-reduction scratch (reuses s2 area; s2 no longer needed)
    float* colsum = (float*)(smem + 196608);
    float* colmax = colsum + 256;
    if (outF) {
        __syncthreads();
        if (tid < 256) { colsum[tid] = 0.f; colmax[tid] = 0.f; }
        __syncthreads();
    }

    int grp = lane >> 2, qp = lane & 3;
#pragma unroll
    for (int h = 0; h < 2; h++) {
        int mloc = i0 + wm * 32 + h * 16 + grp;
        float li0 = g_linv[b * NN + mloc];
        float li1 = g_linv[b * NN + mloc + 8];
        size_t rb0 = (size_t)(b * NN + mloc) * HH;
        size_t rb1 = (size_t)(b * NN + mloc + 8) * HH;
#pragma unroll
        for (int t = 0; t < 8; t++) {
            int n = wn * 64 + t * 8 + qp * 2;
            float v00 = fmaxf(acc[h][t][0] * li0, 0.f);
            float v01 = fmaxf(acc[h][t][1] * li0, 0.f);
            float v10 = fmaxf(acc[h][t][2] * li1, 0.f);
            float v11 = fmaxf(acc[h][t][3] * li1, 0.f);
            if (outF) {
                float2 f0 = {v00, v01}, f1 = {v10, v11};
                *(float2*)(outF + rb0 + n) = f0;
                *(float2*)(outF + rb1 + n) = f1;
                atomicAdd(&colsum[n], v00 + v10);
                atomicAdd(&colsum[n + 1], v01 + v11);
                atomicMax((int*)&colmax[n], __float_as_int(fmaxf(v00, v10)));
                atomicMax((int*)&colmax[n + 1], __float_as_int(fmaxf(v01, v11)));
            }
            uint32_t hw, lw;
            split2(v00, v01, hw, lw);
            *(uint32_t*)(Ohi + rb0 + n) = hw;
            *(uint32_t*)(Olo + rb0 + n) = lw;
            split2(v10, v11, hw, lw);
            *(uint32_t*)(Ohi + rb1 + n) = hw;
            *(uint32_t*)(Olo + rb1 + n) = lw;
        }
    }
    if (outF) {
        __syncthreads();
        if (tid < 256) {
            atomicAdd(&g_sum[b * HH + tid], colsum[tid]);
            atomicMax((int*)&g_max[b * HH + tid], __float_as_int(colmax[tid]));
        }
    }
}

// ---------------- pooling init + MLP ---------------------------------------
__global__ void zero_pool_kernel()
{
    int i = blockIdx.x * blockDim.x + threadIdx.x;
    if (i < BB * HH) { g_sum[i] = 0.f; g_max[i] = 0.f; }
}

__global__ void mlp_kernel(const float* __restrict__ W1,
                           const float* __restrict__ b1,
                           const float* __restrict__ W2,
                           const float* __restrict__ b2,
                           float* __restrict__ gout)
{
    __shared__ float p[HH];
    __shared__ float y1[HH];
    int b = blockIdx.x, t = threadIdx.x;
    p[t] = g_sum[b * HH + t] * (1.f / (float)NN) + g_max[b * HH + t];
    __syncthreads();
    float acc = b1[t];
#pragma unroll 4
    for (int k = 0; k < HH; k++)
        acc = fmaf(p[k], W1[(size_t)k * HH + t], acc);
    y1[t] = fmaxf(acc, 0.f);
    __syncthreads();
    float acc2 = b2[t];
#pragma unroll 4
    for (int k = 0; k < HH; k++)
        acc2 = fmaf(y1[k], W2[(size_t)k * HH + t], acc2);
    gout[b * HH + t] = acc2;
}

// ---------------- launch ---------------------------------------------------
extern "C" void kernel_launch(void* const* d_in, const int* in_sizes, int n_in,
                              void* d_out, int out_size)
{
    const float* nf   = (const float*)d_in[0];
    const float* adj  = (const float*)d_in[1];
    const float* embW = (const float*)d_in[2];
    const float* embb = (const float*)d_in[3];
    const float* W0   = (const float*)d_in[4];
    const float* a10  = (const float*)d_in[5];
    const float* a20  = (const float*)d_in[6];
    const float* W1   = (const float*)d_in[7];
    const float* a11  = (const float*)d_in[8];
    const float* a21  = (const float*)d_in[9];
    const float* gW1  = (const float*)d_in[10];
    const float* gb1  = (const float*)d_in[11];
    const float* gW2  = (const float*)d_in[12];
    const float* gb2  = (const float*)d_in[13];

    float* outx = (float*)d_out;
    float* outg = outx + (size_t)BB * NN * HH;

    bf16 *ahi, *alo, *chi, *clo, *bhi, *blo, *whi, *wlo;
    uint32_t* bitsp;
    cudaGetSymbolAddress((void**)&ahi, g_ahi);
    cudaGetSymbolAddress((void**)&alo, g_alo);
    cudaGetSymbolAddress((void**)&chi, g_chi);
    cudaGetSymbolAddress((void**)&clo, g_clo);
    cudaGetSymbolAddress((void**)&bhi, g_bhi);
    cudaGetSymbolAddress((void**)&blo, g_blo);
    cudaGetSymbolAddress((void**)&whi, g_whi);
    cudaGetSymbolAddress((void**)&wlo, g_wlo);
    cudaGetSymbolAddress((void**)&bitsp, g_adjbits);

    const int SM_G = 2 * 98304 + 1024;              // 197632
    const int SM_A = 2 * 32768 + 2 * 65536 + 4096;  // 200704
    cudaFuncSetAttribute(gemm_mma_kernel,
                         cudaFuncAttributeMaxDynamicSharedMemorySize, SM_G);
    cudaFuncSetAttribute(attn_mma_kernel,
                         cudaFuncAttributeMaxDynamicSharedMemorySize, SM_A);

    const int M = BB * NN;

    packbits_kernel<<<M / 8, 256>>>(adj, bitsp);

    // ---- embed: x = nf @ embW + embb ----
    split_kernel<<<(M * FIN / 4 + 255) / 256, 256>>>(nf, ahi, alo, M * FIN / 4);
    split_kernel<<<(FIN * HH / 4 + 255) / 256, 256>>>(embW, whi, wlo,
                                                      FIN * HH / 4);
    gemm_mma_kernel<<<M / 128, 512, SM_G>>>(ahi, alo, whi, wlo, embb,
                                            nullptr, nullptr, chi, clo, FIN);

    // ---- GAT layer 0 ----
    split_kernel<<<(HH * HH / 4 + 255) / 256, 256>>>(W0, whi, wlo, HH * HH / 4);
    gemm_mma_kernel<<<M / 128, 512, SM_G>>>(chi, clo, whi, wlo, nullptr,
                                            a10, a20, bhi, blo, HH);
    stats_kernel<<<M / 8, 256>>>(bitsp);
    attn_mma_kernel<<<BB * 8, 512, SM_A>>>(bitsp, bhi, blo, nullptr, ahi, alo);

    // ---- GAT layer 1 (pool fused into attn epilogue) ----
    zero_pool_kernel<<<(BB * HH + 255) / 256, 256>>>();
    split_kernel<<<(HH * HH / 4 + 255) / 256, 256>>>(W1, whi, wlo, HH * HH / 4);
    gemm_mma_kernel<<<M / 128, 512, SM_G>>>(ahi, alo, whi, wlo, nullptr,
                                            a11, a21, bhi, blo, HH);
    stats_kernel<<<M / 8, 256>>>(bitsp);
    attn_mma_kernel<<<BB * 8, 512, SM_A>>>(bitsp, bhi, blo, outx, chi, clo);

    // ---- MLP ----
    mlp_kernel<<<BB, 256>>>(gW1, gb1, gW2, gb2, outg);
}

// round 10
// speedup vs baseline: 1.2034x; 1.2034x over previous
#include <cuda_runtime.h>
#include <cuda_fp16.h>
#include <math.h>
#include <stdint.h>

#define BB 16
#define NN 1024
#define FIN 64
#define HH 256
#define NEGV (-9e15f)
#define LALPHA 0.2f

typedef __half fp16;

// ---------------- scratch (device globals: no allocation allowed) ----------
__device__ __align__(256) fp16 g_ahi[BB * NN * HH];
__device__ __align__(256) fp16 g_alo[BB * NN * HH];
__device__ __align__(256) fp16 g_chi[BB * NN * HH];
__device__ __align__(256) fp16 g_clo[BB * NN * HH];
__device__ __align__(256) fp16 g_bhi[BB * NN * HH];       // h single fp16
__device__ __align__(256) fp16 g_whi[HH * HH];
__device__ __align__(256) fp16 g_wlo[HH * HH];
__device__ __align__(256) uint32_t g_adjbits[BB * NN * (NN / 32)];
__device__ __align__(256) float g_s1[BB * NN];
__device__ __align__(256) float g_s2[BB * NN];
__device__ __align__(256) float g_m[BB * NN];
__device__ __align__(256) float g_linv[BB * NN];
__device__ __align__(256) float g_sum[BB * HH];
__device__ __align__(256) float g_max[BB * HH];

// ---------------- helpers --------------------------------------------------
__device__ __forceinline__ uint32_t swz(uint32_t o) {
    return o ^ ((o >> 3) & 0x70);
}
__device__ __forceinline__ uint32_t su32(const void* p) {
    uint32_t a;
    asm("{ .reg .u64 t; cvta.to.shared.u64 t, %1; cvt.u32.u64 %0, t; }"
        : "=r"(a) : "l"(p));
    return a;
}
#define CP16(d, s)                                                            \
    asm volatile("cp.async.cg.shared.global [%0], [%1], 16;" ::"r"(d), "l"(s))
#define CPCOMMIT() asm volatile("cp.async.commit_group;" ::: "memory")
#define CPWAIT0() asm volatile("cp.async.wait_group 0;" ::: "memory")

__device__ __forceinline__ void ldsm4(uint32_t addr, uint32_t* r) {
    asm volatile("ldmatrix.sync.aligned.m8n8.x4.shared.b16 {%0,%1,%2,%3}, [%4];"
                 : "=r"(r[0]), "=r"(r[1]), "=r"(r[2]), "=r"(r[3]) : "r"(addr));
}
__device__ __forceinline__ void ldsm4t(uint32_t addr, uint32_t* r) {
    asm volatile("ldmatrix.sync.aligned.m8n8.x4.trans.shared.b16 {%0,%1,%2,%3}, [%4];"
                 : "=r"(r[0]), "=r"(r[1]), "=r"(r[2]), "=r"(r[3]) : "r"(addr));
}
__device__ __forceinline__ void mma16816(float* c, const uint32_t* a,
                                         const uint32_t* b) {
    asm volatile(
        "mma.sync.aligned.m16n8k16.row.col.f32.f16.f16.f32 "
        "{%0,%1,%2,%3}, {%4,%5,%6,%7}, {%8,%9}, {%0,%1,%2,%3};"
        : "+f"(c[0]), "+f"(c[1]), "+f"(c[2]), "+f"(c[3])
        : "r"(a[0]), "r"(a[1]), "r"(a[2]), "r"(a[3]), "r"(b[0]), "r"(b[1]));
}

// 3-pass hi/lo chunk (GEMM): A[128|64][64] hi/lo, B panel [64][64] hi/lo.
__device__ __forceinline__ void mma_chunk3(uint32_t aHi, uint32_t aLo,
                                           uint32_t bHi, uint32_t bLo,
                                           int wm, int lane,
                                           float acc[2][8][4])
{
    int rA = lane & 15;
    int cA = (lane >> 4) * 16;
#pragma unroll
    for (int ks = 0; ks < 4; ks++) {
        uint32_t ah[2][4], al[2][4], bb[4][4];
#pragma unroll
        for (int h = 0; h < 2; h++) {
            uint32_t off = swz((uint32_t)(wm * 32 + h * 16 + rA) * 128 +
                               ks * 32 + cA);
            ldsm4(aHi + off, ah[h]);
            ldsm4(aLo + off, al[h]);
        }
#pragma unroll
        for (int t = 0; t < 4; t++) {
            uint32_t off = swz((uint32_t)(ks * 16 + rA) * 128 + t * 32 + cA);
            ldsm4t(bHi + off, bb[t]);
        }
#pragma unroll
        for (int h = 0; h < 2; h++)
#pragma unroll
            for (int t = 0; t < 4; t++) {
                mma16816(acc[h][2 * t], ah[h], bb[t]);
                mma16816(acc[h][2 * t + 1], ah[h], bb[t] + 2);
            }
#pragma unroll
        for (int h = 0; h < 2; h++)
#pragma unroll
            for (int t = 0; t < 4; t++) {
                mma16816(acc[h][2 * t], al[h], bb[t]);
                mma16816(acc[h][2 * t + 1], al[h], bb[t] + 2);
            }
#pragma unroll
        for (int t = 0; t < 4; t++) {
            uint32_t off = swz((uint32_t)(ks * 16 + rA) * 128 + t * 32 + cA);
            ldsm4t(bLo + off, bb[t]);
        }
#pragma unroll
        for (int h = 0; h < 2; h++)
#pragma unroll
            for (int t = 0; t < 4; t++) {
                mma16816(acc[h][2 * t], ah[h], bb[t]);
                mma16816(acc[h][2 * t + 1], ah[h], bb[t] + 2);
            }
    }
}

// 2-pass chunk (ATTN): A = P hi/lo, B = H single fp16.
__device__ __forceinline__ void mma_chunk2(uint32_t aHi, uint32_t aLo,
                                           uint32_t bH, int wm, int lane,
                                           float acc[2][8][4])
{
    int rA = lane & 15;
    int cA = (lane >> 4) * 16;
#pragma unroll
    for (int ks = 0; ks < 4; ks++) {
        uint32_t ah[2][4], al[2][4], bb[4][4];
#pragma unroll
        for (int h = 0; h < 2; h++) {
            uint32_t off = swz((uint32_t)(wm * 32 + h * 16 + rA) * 128 +
                               ks * 32 + cA);
            ldsm4(aHi + off, ah[h]);
            ldsm4(aLo + off, al[h]);
        }
#pragma unroll
        for (int t = 0; t < 4; t++) {
            uint32_t off = swz((uint32_t)(ks * 16 + rA) * 128 + t * 32 + cA);
            ldsm4t(bH + off, bb[t]);
        }
#pragma unroll
        for (int h = 0; h < 2; h++)
#pragma unroll
            for (int t = 0; t < 4; t++) {
                mma16816(acc[h][2 * t], ah[h], bb[t]);
                mma16816(acc[h][2 * t + 1], ah[h], bb[t] + 2);
            }
#pragma unroll
        for (int h = 0; h < 2; h++)
#pragma unroll
            for (int t = 0; t < 4; t++) {
                mma16816(acc[h][2 * t], al[h], bb[t]);
                mma16816(acc[h][2 * t + 1], al[h], bb[t] + 2);
            }
    }
}

__device__ __forceinline__ void split2h(float v0, float v1, uint32_t& hw,
                                        uint32_t& lw) {
    __half2 h2 = __floats2half2_rn(v0, v1);
    float r0 = v0 - __half2float(__low2half(h2));
    float r1 = v1 - __half2float(__high2half(h2));
    __half2 l2 = __floats2half2_rn(r0, r1);
    hw = *(uint32_t*)&h2;
    lw = *(uint32_t*)&l2;
}

// ---------------- prep kernels ---------------------------------------------
__global__ void packbits_kernel(const float* __restrict__ adj,
                                uint32_t* __restrict__ bits)
{
    int row = (blockIdx.x * blockDim.x + threadIdx.x) >> 5;
    int lane = threadIdx.x & 31;
    if (row >= BB * NN) return;
    const float* ar = adj + (size_t)row * NN;
    uint32_t myword = 0;
#pragma unroll
    for (int wd = 0; wd < 32; wd++) {
        uint32_t v = __ballot_sync(0xffffffffu, ar[wd * 32 + lane] > 0.f);
        if (lane == wd) myword = v;
    }
    bits[(size_t)row * 32 + lane] = myword;
}

__global__ void split_kernel(const float* __restrict__ X,
                             fp16* __restrict__ Xh, fp16* __restrict__ Xl,
                             int n4)
{
    int i = blockIdx.x * blockDim.x + threadIdx.x;
    if (i >= n4) return;
    float4 v = *(const float4*)(X + (size_t)i * 4);
    uint2 hw, lw;
    split2h(v.x, v.y, hw.x, lw.x);
    split2h(v.z, v.w, hw.y, lw.y);
    *(uint2*)(Xh + (size_t)i * 4) = hw;
    *(uint2*)(Xl + (size_t)i * 4) = lw;
}

// ---------------- pipelined GEMM: C = A[M,K] @ B[K,256] (+bias) ------------
__device__ __forceinline__ void gemm_load_chunk(
    uint32_t sb, int st, int tid, int m0, int k0,
    const fp16* Ah, const fp16* Al, const fp16* Bh, const fp16* Bl, int K)
{
    uint32_t s0 = sb + st * 98304;
#pragma unroll
    for (int i = tid; i < 1024; i += 512) {
        int r = i >> 3, cc = i & 7;
        size_t g = (size_t)(m0 + r) * K + k0 + cc * 8;
        uint32_t so = s0 + swz(r * 128 + cc * 16);
        CP16(so, Ah + g);
        CP16(so + 16384, Al + g);
    }
#pragma unroll
    for (int i = tid; i < 2048; i += 512) {
        int r = i >> 5, c32 = i & 31;
        int p = c32 >> 3, cc = c32 & 7;
        size_t g = (size_t)(k0 + r) * 256 + c32 * 8;
        uint32_t so = s0 + 32768 + p * 8192 + swz(r * 128 + cc * 16);
        CP16(so, Bh + g);
        CP16(so + 32768, Bl + g);
    }
}

__global__ void __launch_bounds__(512, 1) gemm_mma_kernel(
    const fp16* __restrict__ Ah, const fp16* __restrict__ Al,
    const fp16* __restrict__ Bh, const fp16* __restrict__ Bl,
    const float* __restrict__ bias, const float* __restrict__ a1,
    const float* __restrict__ a2, fp16* __restrict__ Chi,
    fp16* __restrict__ Clo, int K)
{
    extern __shared__ __align__(1024) char smem[];
    uint32_t sb = su32(smem);
    int tid = threadIdx.x, lane = tid & 31, w = tid >> 5;
    int wm = w >> 2, wn = w & 3;
    int m0 = blockIdx.x * 128;
    int nch = K >> 6;

    float acc[2][8][4];
#pragma unroll
    for (int h = 0; h < 2; h++)
#pragma unroll
        for (int t = 0; t < 8; t++)
#pragma unroll
            for (int e = 0; e < 4; e++) acc[h][t][e] = 0.f;

    gemm_load_chunk(sb, 0, tid, m0, 0, Ah, Al, Bh, Bl, K);
    CPCOMMIT();

    for (int c = 0; c < nch; c++) {
        int st = c & 1;
        CPWAIT0();
        __syncthreads();
        if (c + 1 < nch) {
            gemm_load_chunk(sb, st ^ 1, tid, m0, (c + 1) << 6, Ah, Al, Bh, Bl, K);
            CPCOMMIT();
        }
        mma_chunk3(sb + st * 98304, sb + st * 98304 + 16384,
                   sb + st * 98304 + 32768 + wn * 8192,
                   sb + st * 98304 + 65536 + wn * 8192, wm, lane, acc);
    }

    // fused rowdot scratch
    float* s1s = (float*)(smem + 196608);
    float* s2s = s1s + 128;
    if (tid < 256) s1s[tid] = 0.f;
    __syncthreads();

    int grp = lane >> 2, qp = lane & 3;
#pragma unroll
    for (int h = 0; h < 2; h++) {
        int mA = m0 + wm * 32 + h * 16 + grp;
        float p1a = 0.f, p1b = 0.f, p2a = 0.f, p2b = 0.f;
#pragma unroll
        for (int t = 0; t < 8; t++) {
            int n = wn * 64 + t * 8 + qp * 2;
            float b0 = bias ? bias[n] : 0.f;
            float b1 = bias ? bias[n + 1] : 0.f;
            float v00 = acc[h][t][0] + b0, v01 = acc[h][t][1] + b1;
            float v10 = acc[h][t][2] + b0, v11 = acc[h][t][3] + b1;
            size_t o0 = (size_t)mA * HH + n;
            size_t o1 = (size_t)(mA + 8) * HH + n;
            uint32_t hw, lw;
            split2h(v00, v01, hw, lw);
            *(uint32_t*)(Chi + o0) = hw;
            if (Clo) *(uint32_t*)(Clo + o0) = lw;
            split2h(v10, v11, hw, lw);
            *(uint32_t*)(Chi + o1) = hw;
            if (Clo) *(uint32_t*)(Clo + o1) = lw;
            if (a1) {
                float a1v0 = a1[n], a1v1 = a1[n + 1];
                float a2v0 = a2[n], a2v1 = a2[n + 1];
                p1a += v00 * a1v0 + v01 * a1v1;
                p1b += v10 * a1v0 + v11 * a1v1;
                p2a += v00 * a2v0 + v01 * a2v1;
                p2b += v10 * a2v0 + v11 * a2v1;
            }
        }
        if (a1) {
            int lr = wm * 32 + h * 16 + grp;
            atomicAdd(&s1s[lr], p1a);
            atomicAdd(&s1s[lr + 8], p1b);
            atomicAdd(&s2s[lr], p2a);
            atomicAdd(&s2s[lr + 8], p2b);
        }
    }
    if (a1) {
        __syncthreads();
        if (tid < 128) {
            g_s1[m0 + tid] = s1s[tid];
            g_s2[m0 + tid] = s2s[tid];
        }
    }
}

// ---------------- softmax stats from bitmask -------------------------------
__global__ void stats_kernel(const uint32_t* __restrict__ bits)
{
    int warp_in = threadIdx.x >> 5;
    int lane = threadIdx.x & 31;
    int row = blockIdx.x * 8 + warp_in;
    int b = row >> 10;
    uint32_t w = bits[(size_t)row * 32 + lane];
    const float* s2b = g_s2 + (b << 10);
    float s1v = g_s1[row];
    float e[32];
    float m = -INFINITY;
#pragma unroll
    for (int jj = 0; jj < 32; jj++) {
        int j = jj * 32 + lane;
        uint32_t wj = __shfl_sync(0xffffffffu, w, jj);
        float t = s1v + s2b[j];
        t = (t >= 0.f) ? t : LALPHA * t;
        t = ((wj >> lane) & 1u) ? t : NEGV;
        e[jj] = t;
        m = fmaxf(m, t);
    }
#pragma unroll
    for (int off = 16; off; off >>= 1)
        m = fmaxf(m, __shfl_xor_sync(0xffffffffu, m, off));
    float l = 0.f;
#pragma unroll
    for (int jj = 0; jj < 32; jj++) l += __expf(e[jj] - m);
#pragma unroll
    for (int off = 16; off; off >>= 1)
        l += __shfl_xor_sync(0xffffffffu, l, off);
    if (lane == 0) { g_m[row] = m; g_linv[row] = 1.f / l; }
}

// ---------------- pipelined attention (2 CTAs/SM, 64-row tiles) ------------
// smem: P_HI 2x8K @0 | P_LO 2x8K @16384 | H 2x32K @32768 | s2/pool @98304.
__device__ __forceinline__ void attn_load_h(
    uint32_t sb, int st, int tid, int b, int j0, const fp16* Hh)
{
    uint32_t s0 = sb + 32768 + st * 32768;
#pragma unroll
    for (int i = tid; i < 2048; i += 256) {
        int r = i >> 5, c32 = i & 31;
        int p = c32 >> 3, cc = c32 & 7;
        size_t g = (size_t)(b * NN + j0 + r) * 256 + c32 * 8;
        uint32_t so = s0 + p * 8192 + swz(r * 128 + cc * 16);
        CP16(so, Hh + g);
    }
}

__global__ void __launch_bounds__(256, 2) attn_mma_kernel(
    const uint32_t* __restrict__ bits, const fp16* __restrict__ Hh,
    float* __restrict__ outF, fp16* __restrict__ Ohi, fp16* __restrict__ Olo)
{
    extern __shared__ __align__(1024) char smem[];
    uint32_t sb = su32(smem);
    int tid = threadIdx.x, lane = tid & 31, w = tid >> 5;
    int wm = w >> 2, wn = w & 3;
    int b = blockIdx.x >> 4;
    int i0 = (blockIdx.x & 15) << 6;

    float* s2s = (float*)(smem + 98304);

    int prow = tid >> 2;
    int pj = (tid & 3) * 16;
    int growi = b * NN + i0 + prow;
    float s1v = g_s1[growi];
    float mv = g_m[growi];
    const uint32_t* brow = bits + (size_t)growi * 32;

    for (int i = tid; i < NN; i += 256) s2s[i] = g_s2[b * NN + i];
    attn_load_h(sb, 0, tid, b, 0, Hh);
    CPCOMMIT();
    __syncthreads();

#define BUILD_P(cc, st)                                                        \
    do {                                                                       \
        int j0_ = (cc) << 6;                                                   \
        uint32_t word = brow[(j0_ >> 5) + (pj >> 5)];                          \
        int bitbase = pj & 31;                                                 \
        uint4 hw, lw, hw2, lw2;                                                \
        uint32_t* hp = (uint32_t*)&hw;                                         \
        uint32_t* lp = (uint32_t*)&lw;                                         \
        uint32_t* hp2 = (uint32_t*)&hw2;                                       \
        uint32_t* lp2 = (uint32_t*)&lw2;                                       \
        _Pragma("unroll") for (int q = 0; q < 8; q++) {                        \
            float e0 = s1v + s2s[j0_ + pj + 2 * q];                            \
            float e1 = s1v + s2s[j0_ + pj + 2 * q + 1];                        \
            e0 = (e0 >= 0.f) ? e0 : LALPHA * e0;                               \
            e1 = (e1 >= 0.f) ? e1 : LALPHA * e1;                               \
            float p0 = ((word >> (bitbase + 2 * q)) & 1u) ? __expf(e0 - mv) : 0.f; \
            float p1 = ((word >> (bitbase + 2 * q + 1)) & 1u) ? __expf(e1 - mv) : 0.f; \
            uint32_t hww, lww;                                                 \
            split2h(p0, p1, hww, lww);                                         \
            if (q < 4) { hp[q] = hww; lp[q] = lww; }                           \
            else { hp2[q - 4] = hww; lp2[q - 4] = lww; }                       \
        }                                                                      \
        uint32_t o = (uint32_t)prow * 128 + pj * 2;                            \
        uint32_t so0 = swz(o), so1 = swz(o + 16);                              \
        char* pb = smem + (st) * 8192;                                         \
        *(uint4*)(pb + so0) = hw;                                              \
        *(uint4*)(pb + 16384 + so0) = lw;                                      \
        *(uint4*)(pb + so1) = hw2;                                             \
        *(uint4*)(pb + 16384 + so1) = lw2;                                     \
    } while (0)

    BUILD_P(0, 0);

    float acc[2][8][4];
#pragma unroll
    for (int h = 0; h < 2; h++)
#pragma unroll
        for (int t = 0; t < 8; t++)
#pragma unroll
            for (int e = 0; e < 4; e++) acc[h][t][e] = 0.f;

    for (int c = 0; c < 16; c++) {
        int st = c & 1;
        CPWAIT0();
        __syncthreads();
        if (c < 15) {
            attn_load_h(sb, st ^ 1, tid, b, (c + 1) << 6, Hh);
            CPCOMMIT();
            BUILD_P(c + 1, st ^ 1);
        }
        mma_chunk2(sb + st * 8192, sb + 16384 + st * 8192,
                   sb + 32768 + st * 32768 + wn * 8192, wm, lane, acc);
    }
#undef BUILD_P

    // pooled-reduction scratch (reuses s2 area)
    float* colsum = (float*)(smem + 98304);
    float* colmax = colsum + 256;
    if (outF) {
        __syncthreads();
        if (tid < 256) { colsum[tid] = 0.f; colmax[tid] = 0.f; }
        __syncthreads();
    }

    int grp = lane >> 2, qp = lane & 3;
    float cs[8][2], cm[8][2];
#pragma unroll
    for (int t = 0; t < 8; t++) { cs[t][0] = cs[t][1] = cm[t][0] = cm[t][1] = 0.f; }

#pragma unroll
    for (int h = 0; h < 2; h++) {
        int mloc = i0 + wm * 32 + h * 16 + grp;
        float li0 = g_linv[b * NN + mloc];
        float li1 = g_linv[b * NN + mloc + 8];
        size_t rb0 = (size_t)(b * NN + mloc) * HH;
        size_t rb1 = (size_t)(b * NN + mloc + 8) * HH;
#pragma unroll
        for (int t = 0; t < 8; t++) {
            int n = wn * 64 + t * 8 + qp * 2;
            float v00 = fmaxf(acc[h][t][0] * li0, 0.f);
            float v01 = fmaxf(acc[h][t][1] * li0, 0.f);
            float v10 = fmaxf(acc[h][t][2] * li1, 0.f);
            float v11 = fmaxf(acc[h][t][3] * li1, 0.f);
            if (outF) {
                float2 f0 = {v00, v01}, f1 = {v10, v11};
                *(float2*)(outF + rb0 + n) = f0;
                *(float2*)(outF + rb1 + n) = f1;
                cs[t][0] += v00 + v10;
                cs[t][1] += v01 + v11;
                cm[t][0] = fmaxf(cm[t][0], fmaxf(v00, v10));
                cm[t][1] = fmaxf(cm[t][1], fmaxf(v01, v11));
            }
            if (Ohi) {
                uint32_t hw, lw;
                split2h(v00, v01, hw, lw);
                *(uint32_t*)(Ohi + rb0 + n) = hw;
                *(uint32_t*)(Olo + rb0 + n) = lw;
                split2h(v10, v11, hw, lw);
                *(uint32_t*)(Ohi + rb1 + n) = hw;
                *(uint32_t*)(Olo + rb1 + n) = lw;
            }
        }
    }
    if (outF) {
#pragma unroll
        for (int t = 0; t < 8; t++) {
            int n = wn * 64 + t * 8 + qp * 2;
            atomicAdd(&colsum[n], cs[t][0]);
            atomicAdd(&colsum[n + 1], cs[t][1]);
            atomicMax((int*)&colmax[n], __float_as_int(cm[t][0]));
            atomicMax((int*)&colmax[n + 1], __float_as_int(cm[t][1]));
        }
        __syncthreads();
        if (tid < 256) {
            atomicAdd(&g_sum[b * HH + tid], colsum[tid]);
            atomicMax((int*)&g_max[b * HH + tid], __float_as_int(colmax[tid]));
        }
    }
}

// ---------------- pooling init + MLP ---------------------------------------
__global__ void zero_pool_kernel()
{
    int i = blockIdx.x * blockDim.x + threadIdx.x;
    if (i < BB * HH) { g_sum[i] = 0.f; g_max[i] = 0.f; }
}

__global__ void mlp_kernel(const float* __restrict__ W1,
                           const float* __restrict__ b1,
                           const float* __restrict__ W2,
                           const float* __restrict__ b2,
                           float* __restrict__ gout)
{
    __shared__ float p[HH];
    __shared__ float y1[HH];
    int b = blockIdx.x, t = threadIdx.x;
    p[t] = g_sum[b * HH + t] * (1.f / (float)NN) + g_max[b * HH + t];
    __syncthreads();
    float acc = b1[t];
#pragma unroll 4
    for (int k = 0; k < HH; k++)
        acc = fmaf(p[k], W1[(size_t)k * HH + t], acc);
    y1[t] = fmaxf(acc, 0.f);
    __syncthreads();
    float acc2 = b2[t];
#pragma unroll 4
    for (int k = 0; k < HH; k++)
        acc2 = fmaf(y1[k], W2[(size_t)k * HH + t], acc2);
    gout[b * HH + t] = acc2;
}

// ---------------- launch ---------------------------------------------------
extern "C" void kernel_launch(void* const* d_in, const int* in_sizes, int n_in,
                              void* d_out, int out_size)
{
    const float* nf   = (const float*)d_in[0];
    const float* adj  = (const float*)d_in[1];
    const float* embW = (const float*)d_in[2];
    const float* embb = (const float*)d_in[3];
    const float* W0   = (const float*)d_in[4];
    const float* a10  = (const float*)d_in[5];
    const float* a20  = (const float*)d_in[6];
    const float* W1   = (const float*)d_in[7];
    const float* a11  = (const float*)d_in[8];
    const float* a21  = (const float*)d_in[9];
    const float* gW1  = (const float*)d_in[10];
    const float* gb1  = (const float*)d_in[11];
    const float* gW2  = (const float*)d_in[12];
    const float* gb2  = (const float*)d_in[13];

    float* outx = (float*)d_out;
    float* outg = outx + (size_t)BB * NN * HH;

    fp16 *ahi, *alo, *chi, *clo, *bhi, *whi, *wlo;
    uint32_t* bitsp;
    cudaGetSymbolAddress((void**)&ahi, g_ahi);
    cudaGetSymbolAddress((void**)&alo, g_alo);
    cudaGetSymbolAddress((void**)&chi, g_chi);
    cudaGetSymbolAddress((void**)&clo, g_clo);
    cudaGetSymbolAddress((void**)&bhi, g_bhi);
    cudaGetSymbolAddress((void**)&whi, g_whi);
    cudaGetSymbolAddress((void**)&wlo, g_wlo);
    cudaGetSymbolAddress((void**)&bitsp, g_adjbits);

    const int SM_G = 2 * 98304 + 1024;      // 197632
    const int SM_A = 98304 + 4096;          // 102400 (2 CTAs/SM)
    cudaFuncSetAttribute(gemm_mma_kernel,
                         cudaFuncAttributeMaxDynamicSharedMemorySize, SM_G);
    cudaFuncSetAttribute(attn_mma_kernel,
                         cudaFuncAttributeMaxDynamicSharedMemorySize, SM_A);

    const int M = BB * NN;

    packbits_kernel<<<M / 8, 256>>>(adj, bitsp);

    // ---- embed: x = nf @ embW + embb ----
    split_kernel<<<(M * FIN / 4 + 255) / 256, 256>>>(nf, ahi, alo, M * FIN / 4);
    split_kernel<<<(FIN * HH / 4 + 255) / 256, 256>>>(embW, whi, wlo,
                                                      FIN * HH / 4);
    gemm_mma_kernel<<<M / 128, 512, SM_G>>>(ahi, alo, whi, wlo, embb,
                                            nullptr, nullptr, chi, clo, FIN);

    // ---- GAT layer 0 ----
    split_kernel<<<(HH * HH / 4 + 255) / 256, 256>>>(W0, whi, wlo, HH * HH / 4);
    gemm_mma_kernel<<<M / 128, 512, SM_G>>>(chi, clo, whi, wlo, nullptr,
                                            a10, a20, bhi, nullptr, HH);
    stats_kernel<<<M / 8, 256>>>(bitsp);
    attn_mma_kernel<<<BB * 16, 256, SM_A>>>(bitsp, bhi, nullptr, ahi, alo);

    // ---- GAT layer 1 (pool fused into attn epilogue) ----
    zero_pool_kernel<<<(BB * HH + 255) / 256, 256>>>();
    split_kernel<<<(HH * HH / 4 + 255) / 256, 256>>>(W1, whi, wlo, HH * HH / 4);
    gemm_mma_kernel<<<M / 128, 512, SM_G>>>(ahi, alo, whi, wlo, nullptr,
                                            a11, a21, bhi, nullptr, HH);
    stats_kernel<<<M / 8, 256>>>(bitsp);
    attn_mma_kernel<<<BB * 16, 256, SM_A>>>(bitsp, bhi, outx, nullptr, nullptr);

    // ---- MLP ----
    mlp_kernel<<<BB, 256>>>(gW1, gb1, gW2, gb2, outg);
}

// round 11
// speedup vs baseline: 1.4141x; 1.1750x over previous
#include <cuda_runtime.h>
#include <cuda_fp16.h>
#include <math.h>
#include <stdint.h>

#define BB 16
#define NN 1024
#define FIN 64
#define HH 256
#define NEGV (-9e15f)
#define LALPHA 0.2f

typedef __half fp16;

// ---------------- scratch (device globals: no allocation allowed) ----------
__device__ __align__(256) fp16 g_ahi[BB * NN * HH];
__device__ __align__(256) fp16 g_alo[BB * NN * HH];
__device__ __align__(256) fp16 g_chi[BB * NN * HH];
__device__ __align__(256) fp16 g_clo[BB * NN * HH];
__device__ __align__(256) fp16 g_bhi[BB * NN * HH];       // h single fp16
__device__ __align__(256) fp16 g_whi[HH * HH];
__device__ __align__(256) fp16 g_wlo[HH * HH];            // written, unused
__device__ __align__(256) uint32_t g_adjbits[BB * NN * (NN / 32)];
__device__ __align__(256) float g_s1[BB * NN];
__device__ __align__(256) float g_s2[BB * NN];
__device__ __align__(256) float g_m[BB * NN];
__device__ __align__(256) float g_linv[BB * NN];
__device__ __align__(256) float g_sum[BB * HH];
__device__ __align__(256) float g_max[BB * HH];

// ---------------- helpers --------------------------------------------------
__device__ __forceinline__ uint32_t swz(uint32_t o) {
    return o ^ ((o >> 3) & 0x70);
}
__device__ __forceinline__ uint32_t su32(const void* p) {
    uint32_t a;
    asm("{ .reg .u64 t; cvta.to.shared.u64 t, %1; cvt.u32.u64 %0, t; }"
        : "=r"(a) : "l"(p));
    return a;
}
#define CP16(d, s)                                                            \
    asm volatile("cp.async.cg.shared.global [%0], [%1], 16;" ::"r"(d), "l"(s))
#define CPCOMMIT() asm volatile("cp.async.commit_group;" ::: "memory")
#define CPWAIT0() asm volatile("cp.async.wait_group 0;" ::: "memory")

__device__ __forceinline__ void ldsm4(uint32_t addr, uint32_t* r) {
    asm volatile("ldmatrix.sync.aligned.m8n8.x4.shared.b16 {%0,%1,%2,%3}, [%4];"
                 : "=r"(r[0]), "=r"(r[1]), "=r"(r[2]), "=r"(r[3]) : "r"(addr));
}
__device__ __forceinline__ void ldsm4t(uint32_t addr, uint32_t* r) {
    asm volatile("ldmatrix.sync.aligned.m8n8.x4.trans.shared.b16 {%0,%1,%2,%3}, [%4];"
                 : "=r"(r[0]), "=r"(r[1]), "=r"(r[2]), "=r"(r[3]) : "r"(addr));
}
__device__ __forceinline__ void mma16816(float* c, const uint32_t* a,
                                         const uint32_t* b) {
    asm volatile(
        "mma.sync.aligned.m16n8k16.row.col.f32.f16.f16.f32 "
        "{%0,%1,%2,%3}, {%4,%5,%6,%7}, {%8,%9}, {%0,%1,%2,%3};"
        : "+f"(c[0]), "+f"(c[1]), "+f"(c[2]), "+f"(c[3])
        : "r"(a[0]), "r"(a[1]), "r"(a[2]), "r"(a[3]), "r"(b[0]), "r"(b[1]));
}

// 2-pass chunk: A hi/lo [64][64], B single [64][64] panel. (GEMM)
__device__ __forceinline__ void mma_chunk2(uint32_t aHi, uint32_t aLo,
                                           uint32_t bH, int wm, int lane,
                                           float acc[2][8][4])
{
    int rA = lane & 15;
    int cA = (lane >> 4) * 16;
#pragma unroll
    for (int ks = 0; ks < 4; ks++) {
        uint32_t ah[2][4], al[2][4], bb[4][4];
#pragma unroll
        for (int h = 0; h < 2; h++) {
            uint32_t off = swz((uint32_t)(wm * 32 + h * 16 + rA) * 128 +
                               ks * 32 + cA);
            ldsm4(aHi + off, ah[h]);
            ldsm4(aLo + off, al[h]);
        }
#pragma unroll
        for (int t = 0; t < 4; t++) {
            uint32_t off = swz((uint32_t)(ks * 16 + rA) * 128 + t * 32 + cA);
            ldsm4t(bH + off, bb[t]);
        }
#pragma unroll
        for (int h = 0; h < 2; h++)
#pragma unroll
            for (int t = 0; t < 4; t++) {
                mma16816(acc[h][2 * t], ah[h], bb[t]);
                mma16816(acc[h][2 * t + 1], ah[h], bb[t] + 2);
            }
#pragma unroll
        for (int h = 0; h < 2; h++)
#pragma unroll
            for (int t = 0; t < 4; t++) {
                mma16816(acc[h][2 * t], al[h], bb[t]);
                mma16816(acc[h][2 * t + 1], al[h], bb[t] + 2);
            }
    }
}

// 1-pass chunk: A single [64][64], B single [64][64] panel. (ATTN)
__device__ __forceinline__ void mma_chunk1(uint32_t aP, uint32_t bH,
                                           int wm, int lane,
                                           float acc[2][8][4])
{
    int rA = lane & 15;
    int cA = (lane >> 4) * 16;
#pragma unroll
    for (int ks = 0; ks < 4; ks++) {
        uint32_t ah[2][4], bb[4][4];
#pragma unroll
        for (int h = 0; h < 2; h++) {
            uint32_t off = swz((uint32_t)(wm * 32 + h * 16 + rA) * 128 +
                               ks * 32 + cA);
            ldsm4(aP + off, ah[h]);
        }
#pragma unroll
        for (int t = 0; t < 4; t++) {
            uint32_t off = swz((uint32_t)(ks * 16 + rA) * 128 + t * 32 + cA);
            ldsm4t(bH + off, bb[t]);
        }
#pragma unroll
        for (int h = 0; h < 2; h++)
#pragma unroll
            for (int t = 0; t < 4; t++) {
                mma16816(acc[h][2 * t], ah[h], bb[t]);
                mma16816(acc[h][2 * t + 1], ah[h], bb[t] + 2);
            }
    }
}

__device__ __forceinline__ void split2h(float v0, float v1, uint32_t& hw,
                                        uint32_t& lw) {
    __half2 h2 = __floats2half2_rn(v0, v1);
    float r0 = v0 - __half2float(__low2half(h2));
    float r1 = v1 - __half2float(__high2half(h2));
    __half2 l2 = __floats2half2_rn(r0, r1);
    hw = *(uint32_t*)&h2;
    lw = *(uint32_t*)&l2;
}

// ---------------- prep kernels ---------------------------------------------
__global__ void packbits_kernel(const float* __restrict__ adj,
                                uint32_t* __restrict__ bits)
{
    int row = (blockIdx.x * blockDim.x + threadIdx.x) >> 5;
    int lane = threadIdx.x & 31;
    if (row >= BB * NN) return;
    const float* ar = adj + (size_t)row * NN;
    uint32_t myword = 0;
#pragma unroll
    for (int wd = 0; wd < 32; wd++) {
        uint32_t v = __ballot_sync(0xffffffffu, ar[wd * 32 + lane] > 0.f);
        if (lane == wd) myword = v;
    }
    bits[(size_t)row * 32 + lane] = myword;
}

__global__ void split_kernel(const float* __restrict__ X,
                             fp16* __restrict__ Xh, fp16* __restrict__ Xl,
                             int n4)
{
    int i = blockIdx.x * blockDim.x + threadIdx.x;
    if (i >= n4) return;
    float4 v = *(const float4*)(X + (size_t)i * 4);
    uint2 hw, lw;
    split2h(v.x, v.y, hw.x, lw.x);
    split2h(v.z, v.w, hw.y, lw.y);
    *(uint2*)(Xh + (size_t)i * 4) = hw;
    *(uint2*)(Xl + (size_t)i * 4) = lw;
}

// ---------------- pipelined GEMM: C = A[M,K] @ B[K,256] (+bias) ------------
// 64-row tiles, 256 threads, 2 CTAs/SM. A hi/lo, B single fp16 (2-pass).
// Stage (49152 B): A_HI @0 (8K) | A_LO @8192 (8K) | B @16384 (32K, 4 panels).
__device__ __forceinline__ void gemm_load_chunk(
    uint32_t sb, int st, int tid, int m0, int k0,
    const fp16* Ah, const fp16* Al, const fp16* Bh, int K)
{
    uint32_t s0 = sb + st * 49152;
#pragma unroll
    for (int i = tid; i < 512; i += 256) {
        int r = i >> 3, cc = i & 7;
        size_t g = (size_t)(m0 + r) * K + k0 + cc * 8;
        uint32_t so = s0 + swz(r * 128 + cc * 16);
        CP16(so, Ah + g);
        CP16(so + 8192, Al + g);
    }
#pragma unroll
    for (int i = tid; i < 2048; i += 256) {
        int r = i >> 5, c32 = i & 31;
        int p = c32 >> 3, cc = c32 & 7;
        size_t g = (size_t)(k0 + r) * 256 + c32 * 8;
        uint32_t so = s0 + 16384 + p * 8192 + swz(r * 128 + cc * 16);
        CP16(so, Bh + g);
    }
}

__global__ void __launch_bounds__(256, 2) gemm_mma_kernel(
    const fp16* __restrict__ Ah, const fp16* __restrict__ Al,
    const fp16* __restrict__ Bh, const float* __restrict__ bias,
    const float* __restrict__ a1, const float* __restrict__ a2,
    fp16* __restrict__ Chi, fp16* __restrict__ Clo, int K)
{
    extern __shared__ __align__(1024) char smem[];
    uint32_t sb = su32(smem);
    int tid = threadIdx.x, lane = tid & 31, w = tid >> 5;
    int wm = w >> 2, wn = w & 3;
    int m0 = blockIdx.x * 64;
    int nch = K >> 6;

    float acc[2][8][4];
#pragma unroll
    for (int h = 0; h < 2; h++)
#pragma unroll
        for (int t = 0; t < 8; t++)
#pragma unroll
            for (int e = 0; e < 4; e++) acc[h][t][e] = 0.f;

    gemm_load_chunk(sb, 0, tid, m0, 0, Ah, Al, Bh, K);
    CPCOMMIT();

    for (int c = 0; c < nch; c++) {
        int st = c & 1;
        CPWAIT0();
        __syncthreads();
        if (c + 1 < nch) {
            gemm_load_chunk(sb, st ^ 1, tid, m0, (c + 1) << 6, Ah, Al, Bh, K);
            CPCOMMIT();
        }
        mma_chunk2(sb + st * 49152, sb + st * 49152 + 8192,
                   sb + st * 49152 + 16384 + wn * 8192, wm, lane, acc);
    }

    // fused rowdot scratch (64 rows)
    float* s1s = (float*)(smem + 98304);
    float* s2s = s1s + 64;
    if (tid < 128) s1s[tid] = 0.f;
    __syncthreads();

    int grp = lane >> 2, qp = lane & 3;
#pragma unroll
    for (int h = 0; h < 2; h++) {
        int mA = m0 + wm * 32 + h * 16 + grp;
        float p1a = 0.f, p1b = 0.f, p2a = 0.f, p2b = 0.f;
#pragma unroll
        for (int t = 0; t < 8; t++) {
            int n = wn * 64 + t * 8 + qp * 2;
            float b0 = bias ? bias[n] : 0.f;
            float b1 = bias ? bias[n + 1] : 0.f;
            float v00 = acc[h][t][0] + b0, v01 = acc[h][t][1] + b1;
            float v10 = acc[h][t][2] + b0, v11 = acc[h][t][3] + b1;
            size_t o0 = (size_t)mA * HH + n;
            size_t o1 = (size_t)(mA + 8) * HH + n;
            uint32_t hw, lw;
            split2h(v00, v01, hw, lw);
            *(uint32_t*)(Chi + o0) = hw;
            if (Clo) *(uint32_t*)(Clo + o0) = lw;
            split2h(v10, v11, hw, lw);
            *(uint32_t*)(Chi + o1) = hw;
            if (Clo) *(uint32_t*)(Clo + o1) = lw;
            if (a1) {
                float a1v0 = a1[n], a1v1 = a1[n + 1];
                float a2v0 = a2[n], a2v1 = a2[n + 1];
                p1a += v00 * a1v0 + v01 * a1v1;
                p1b += v10 * a1v0 + v11 * a1v1;
                p2a += v00 * a2v0 + v01 * a2v1;
                p2b += v10 * a2v0 + v11 * a2v1;
            }
        }
        if (a1) {
            int lr = wm * 32 + h * 16 + grp;
            atomicAdd(&s1s[lr], p1a);
            atomicAdd(&s1s[lr + 8], p1b);
            atomicAdd(&s2s[lr], p2a);
            atomicAdd(&s2s[lr + 8], p2b);
        }
    }
    if (a1) {
        __syncthreads();
        if (tid < 64) {
            g_s1[m0 + tid] = s1s[tid];
            g_s2[m0 + tid] = s2s[tid];
        }
    }
}

// ---------------- softmax stats from bitmask -------------------------------
__global__ void stats_kernel(const uint32_t* __restrict__ bits)
{
    int warp_in = threadIdx.x >> 5;
    int lane = threadIdx.x & 31;
    int row = blockIdx.x * 8 + warp_in;
    int b = row >> 10;
    uint32_t w = bits[(size_t)row * 32 + lane];
    const float* s2b = g_s2 + (b << 10);
    float s1v = g_s1[row];
    float e[32];
    float m = -INFINITY;
#pragma unroll
    for (int jj = 0; jj < 32; jj++) {
        int j = jj * 32 + lane;
        uint32_t wj = __shfl_sync(0xffffffffu, w, jj);
        float t = s1v + s2b[j];
        t = (t >= 0.f) ? t : LALPHA * t;
        t = ((wj >> lane) & 1u) ? t : NEGV;
        e[jj] = t;
        m = fmaxf(m, t);
    }
#pragma unroll
    for (int off = 16; off; off >>= 1)
        m = fmaxf(m, __shfl_xor_sync(0xffffffffu, m, off));
    float l = 0.f;
#pragma unroll
    for (int jj = 0; jj < 32; jj++) l += __expf(e[jj] - m);
#pragma unroll
    for (int off = 16; off; off >>= 1)
        l += __shfl_xor_sync(0xffffffffu, l, off);
    if (lane == 0) { g_m[row] = m; g_linv[row] = 1.f / l; }
}

// ---------------- pipelined attention (1-pass, 2 CTAs/SM) ------------------
// smem: P stages 2x8192 @0 | H stages 2x32768 @16384 | s2/pool @81920 (4 KB).
__device__ __forceinline__ void attn_load_h(
    uint32_t sb, int st, int tid, int b, int j0, const fp16* Hh)
{
    uint32_t s0 = sb + 16384 + st * 32768;
#pragma unroll
    for (int i = tid; i < 2048; i += 256) {
        int r = i >> 5, c32 = i & 31;
        int p = c32 >> 3, cc = c32 & 7;
        size_t g = (size_t)(b * NN + j0 + r) * 256 + c32 * 8;
        uint32_t so = s0 + p * 8192 + swz(r * 128 + cc * 16);
        CP16(so, Hh + g);
    }
}

__global__ void __launch_bounds__(256, 2) attn_mma_kernel(
    const uint32_t* __restrict__ bits, const fp16* __restrict__ Hh,
    float* __restrict__ outF, fp16* __restrict__ Ohi, fp16* __restrict__ Olo)
{
    extern __shared__ __align__(1024) char smem[];
    uint32_t sb = su32(smem);
    int tid = threadIdx.x, lane = tid & 31, w = tid >> 5;
    int wm = w >> 2, wn = w & 3;
    int b = blockIdx.x >> 4;
    int i0 = (blockIdx.x & 15) << 6;

    float* s2s = (float*)(smem + 81920);

    int prow = tid >> 2;
    int pj = (tid & 3) * 16;
    int growi = b * NN + i0 + prow;
    float s1v = g_s1[growi];
    float mv = g_m[growi];
    const uint32_t* brow = bits + (size_t)growi * 32;

    for (int i = tid; i < NN; i += 256) s2s[i] = g_s2[b * NN + i];
    attn_load_h(sb, 0, tid, b, 0, Hh);
    CPCOMMIT();
    __syncthreads();

#define BUILD_P(cc, st)                                                        \
    do {                                                                       \
        int j0_ = (cc) << 6;                                                   \
        uint32_t word = brow[(j0_ >> 5) + (pj >> 5)];                          \
        int bitbase = pj & 31;                                                 \
        uint4 hw, hw2;                                                         \
        uint32_t* hp = (uint32_t*)&hw;                                         \
        uint32_t* hp2 = (uint32_t*)&hw2;                                       \
        _Pragma("unroll") for (int q = 0; q < 8; q++) {                        \
            float e0 = s1v + s2s[j0_ + pj + 2 * q];                            \
            float e1 = s1v + s2s[j0_ + pj + 2 * q + 1];                        \
            e0 = (e0 >= 0.f) ? e0 : LALPHA * e0;                               \
            e1 = (e1 >= 0.f) ? e1 : LALPHA * e1;                               \
            float p0 = ((word >> (bitbase + 2 * q)) & 1u) ? __expf(e0 - mv) : 0.f; \
            float p1 = ((word >> (bitbase + 2 * q + 1)) & 1u) ? __expf(e1 - mv) : 0.f; \
            __half2 h2 = __floats2half2_rn(p0, p1);                            \
            if (q < 4) hp[q] = *(uint32_t*)&h2;                                \
            else hp2[q - 4] = *(uint32_t*)&h2;                                 \
        }                                                                      \
        uint32_t o = (uint32_t)prow * 128 + pj * 2;                            \
        uint32_t so0 = swz(o), so1 = swz(o + 16);                              \
        char* pb = smem + (st) * 8192;                                         \
        *(uint4*)(pb + so0) = hw;                                              \
        *(uint4*)(pb + so1) = hw2;                                             \
    } while (0)

    BUILD_P(0, 0);

    float acc[2][8][4];
#pragma unroll
    for (int h = 0; h < 2; h++)
#pragma unroll
        for (int t = 0; t < 8; t++)
#pragma unroll
            for (int e = 0; e < 4; e++) acc[h][t][e] = 0.f;

    for (int c = 0; c < 16; c++) {
        int st = c & 1;
        CPWAIT0();
        __syncthreads();
        if (c < 15) {
            attn_load_h(sb, st ^ 1, tid, b, (c + 1) << 6, Hh);
            CPCOMMIT();
            BUILD_P(c + 1, st ^ 1);
        }
        mma_chunk1(sb + st * 8192,
                   sb + 16384 + st * 32768 + wn * 8192, wm, lane, acc);
    }
#undef BUILD_P

    // pooled-reduction scratch (reuses s2 area)
    float* colsum = (float*)(smem + 81920);
    float* colmax = colsum + 256;
    if (outF) {
        __syncthreads();
        if (tid < 256) { colsum[tid] = 0.f; colmax[tid] = 0.f; }
        __syncthreads();
    }

    int grp = lane >> 2, qp = lane & 3;
    float cs[8][2], cm[8][2];
#pragma unroll
    for (int t = 0; t < 8; t++) { cs[t][0] = cs[t][1] = cm[t][0] = cm[t][1] = 0.f; }

#pragma unroll
    for (int h = 0; h < 2; h++) {
        int mloc = i0 + wm * 32 + h * 16 + grp;
        float li0 = g_linv[b * NN + mloc];
        float li1 = g_linv[b * NN + mloc + 8];
        size_t rb0 = (size_t)(b * NN + mloc) * HH;
        size_t rb1 = (size_t)(b * NN + mloc + 8) * HH;
#pragma unroll
        for (int t = 0; t < 8; t++) {
            int n = wn * 64 + t * 8 + qp * 2;
            float v00 = fmaxf(acc[h][t][0] * li0, 0.f);
            float v01 = fmaxf(acc[h][t][1] * li0, 0.f);
            float v10 = fmaxf(acc[h][t][2] * li1, 0.f);
            float v11 = fmaxf(acc[h][t][3] * li1, 0.f);
            if (outF) {
                float2 f0 = {v00, v01}, f1 = {v10, v11};
                *(float2*)(outF + rb0 + n) = f0;
                *(float2*)(outF + rb1 + n) = f1;
                cs[t][0] += v00 + v10;
                cs[t][1] += v01 + v11;
                cm[t][0] = fmaxf(cm[t][0], fmaxf(v00, v10));
                cm[t][1] = fmaxf(cm[t][1], fmaxf(v01, v11));
            }
            if (Ohi) {
                uint32_t hw, lw;
                split2h(v00, v01, hw, lw);
                *(uint32_t*)(Ohi + rb0 + n) = hw;
                *(uint32_t*)(Olo + rb0 + n) = lw;
                split2h(v10, v11, hw, lw);
                *(uint32_t*)(Ohi + rb1 + n) = hw;
                *(uint32_t*)(Olo + rb1 + n) = lw;
            }
        }
    }
    if (outF) {
#pragma unroll
        for (int t = 0; t < 8; t++) {
            int n = wn * 64 + t * 8 + qp * 2;
            atomicAdd(&colsum[n], cs[t][0]);
            atomicAdd(&colsum[n + 1], cs[t][1]);
            atomicMax((int*)&colmax[n], __float_as_int(cm[t][0]));
            atomicMax((int*)&colmax[n + 1], __float_as_int(cm[t][1]));
        }
        __syncthreads();
        if (tid < 256) {
            atomicAdd(&g_sum[b * HH + tid], colsum[tid]);
            atomicMax((int*)&g_max[b * HH + tid], __float_as_int(colmax[tid]));
        }
    }
}

// ---------------- pooling init + MLP ---------------------------------------
__global__ void zero_pool_kernel()
{
    int i = blockIdx.x * blockDim.x + threadIdx.x;
    if (i < BB * HH) { g_sum[i] = 0.f; g_max[i] = 0.f; }
}

__global__ void mlp_kernel(const float* __restrict__ W1,
                           const float* __restrict__ b1,
                           const float* __restrict__ W2,
                           const float* __restrict__ b2,
                           float* __restrict__ gout)
{
    __shared__ float p[HH];
    __shared__ float y1[HH];
    int b = blockIdx.x, t = threadIdx.x;
    p[t] = g_sum[b * HH + t] * (1.f / (float)NN) + g_max[b * HH + t];
    __syncthreads();
    float acc = b1[t];
#pragma unroll 4
    for (int k = 0; k < HH; k++)
        acc = fmaf(p[k], W1[(size_t)k * HH + t], acc);
    y1[t] = fmaxf(acc, 0.f);
    __syncthreads();
    float acc2 = b2[t];
#pragma unroll 4
    for (int k = 0; k < HH; k++)
        acc2 = fmaf(y1[k], W2[(size_t)k * HH + t], acc2);
    gout[b * HH + t] = acc2;
}

// ---------------- launch ---------------------------------------------------
extern "C" void kernel_launch(void* const* d_in, const int* in_sizes, int n_in,
                              void* d_out, int out_size)
{
    const float* nf   = (const float*)d_in[0];
    const float* adj  = (const float*)d_in[1];
    const float* embW = (const float*)d_in[2];
    const float* embb = (const float*)d_in[3];
    const float* W0   = (const float*)d_in[4];
    const float* a10  = (const float*)d_in[5];
    const float* a20  = (const float*)d_in[6];
    const float* W1   = (const float*)d_in[7];
    const float* a11  = (const float*)d_in[8];
    const float* a21  = (const float*)d_in[9];
    const float* gW1  = (const float*)d_in[10];
    const float* gb1  = (const float*)d_in[11];
    const float* gW2  = (const float*)d_in[12];
    const float* gb2  = (const float*)d_in[13];

    float* outx = (float*)d_out;
    float* outg = outx + (size_t)BB * NN * HH;

    fp16 *ahi, *alo, *chi, *clo, *bhi, *whi, *wlo;
    uint32_t* bitsp;
    cudaGetSymbolAddress((void**)&ahi, g_ahi);
    cudaGetSymbolAddress((void**)&alo, g_alo);
    cudaGetSymbolAddress((void**)&chi, g_chi);
    cudaGetSymbolAddress((void**)&clo, g_clo);
    cudaGetSymbolAddress((void**)&bhi, g_bhi);
    cudaGetSymbolAddress((void**)&whi, g_whi);
    cudaGetSymbolAddress((void**)&wlo, g_wlo);
    cudaGetSymbolAddress((void**)&bitsp, g_adjbits);

    const int SM_G = 2 * 49152 + 1024;      // 99328  (2 CTAs/SM)
    const int SM_A = 81920 + 4096;          // 86016  (2 CTAs/SM)
    cudaFuncSetAttribute(gemm_mma_kernel,
                         cudaFuncAttributeMaxDynamicSharedMemorySize, SM_G);
    cudaFuncSetAttribute(attn_mma_kernel,
                         cudaFuncAttributeMaxDynamicSharedMemorySize, SM_A);

    const int M = BB * NN;

    packbits_kernel<<<M / 8, 256>>>(adj, bitsp);

    // ---- embed: x = nf @ embW + embb ----
    split_kernel<<<(M * FIN / 4 + 255) / 256, 256>>>(nf, ahi, alo, M * FIN / 4);
    split_kernel<<<(FIN * HH / 4 + 255) / 256, 256>>>(embW, whi, wlo,
                                                      FIN * HH / 4);
    gemm_mma_kernel<<<M / 64, 256, SM_G>>>(ahi, alo, whi, embb,
                                           nullptr, nullptr, chi, clo, FIN);

    // ---- GAT layer 0 ----
    split_kernel<<<(HH * HH / 4 + 255) / 256, 256>>>(W0, whi, wlo, HH * HH / 4);
    gemm_mma_kernel<<<M / 64, 256, SM_G>>>(chi, clo, whi, nullptr,
                                           a10, a20, bhi, nullptr, HH);
    stats_kernel<<<M / 8, 256>>>(bitsp);
    attn_mma_kernel<<<BB * 16, 256, SM_A>>>(bitsp, bhi, nullptr, ahi, alo);

    // ---- GAT layer 1 (pool fused into attn epilogue) ----
    zero_pool_kernel<<<(BB * HH + 255) / 256, 256>>>();
    split_kernel<<<(HH * HH / 4 + 255) / 256, 256>>>(W1, whi, wlo, HH * HH / 4);
    gemm_mma_kernel<<<M / 64, 256, SM_G>>>(ahi, alo, whi, nullptr,
                                           a11, a21, bhi, nullptr, HH);
    stats_kernel<<<M / 8, 256>>>(bitsp);
    attn_mma_kernel<<<BB * 16, 256, SM_A>>>(bitsp, bhi, outx, nullptr, nullptr);

    // ---- MLP ----
    mlp_kernel<<<BB, 256>>>(gW1, gb1, gW2, gb2, outg);
}

// round 15
// speedup vs baseline: 1.6469x; 1.1646x over previous
#include <cuda_runtime.h>
#include <cuda_fp16.h>
#include <math.h>
#include <stdint.h>

#define BB 16
#define NN 1024
#define FIN 64
#define HH 256
#define NEGV (-9e15f)
#define LALPHA 0.2f

typedef __half fp16;

// ---------------- scratch (device globals: no allocation allowed) ----------
__device__ __align__(256) fp16 g_ahi[BB * NN * HH];
__device__ __align__(256) fp16 g_alo[BB * NN * HH];
__device__ __align__(256) fp16 g_chi[BB * NN * HH];
__device__ __align__(256) fp16 g_clo[BB * NN * HH];
__device__ __align__(256) fp16 g_bhi[BB * NN * HH];       // h single fp16
__device__ __align__(256) fp16 g_whi[HH * HH];
__device__ __align__(256) fp16 g_wlo[HH * HH];            // written, unused
__device__ __align__(256) fp16 g_p[BB * NN * NN];         // P = exp(e-m), 32 MB
__device__ __align__(256) uint32_t g_adjbits[BB * NN * (NN / 32)];
__device__ __align__(256) float g_s1[BB * NN];
__device__ __align__(256) float g_s2[BB * NN];
__device__ __align__(256) float g_linv[BB * NN];
__device__ __align__(256) float g_sum[BB * HH];
__device__ __align__(256) float g_max[BB * HH];

// ---------------- helpers --------------------------------------------------
__device__ __forceinline__ uint32_t swz(uint32_t o) {
    return o ^ ((o >> 3) & 0x70);
}
__device__ __forceinline__ uint32_t su32(const void* p) {
    uint32_t a;
    asm("{ .reg .u64 t; cvta.to.shared.u64 t, %1; cvt.u32.u64 %0, t; }"
        : "=r"(a) : "l"(p));
    return a;
}
#define CP16(d, s)                                                            \
    asm volatile("cp.async.cg.shared.global [%0], [%1], 16;" ::"r"(d), "l"(s))
#define CPCOMMIT() asm volatile("cp.async.commit_group;" ::: "memory")
#define CPWAIT0() asm volatile("cp.async.wait_group 0;" ::: "memory")

__device__ __forceinline__ void ldsm4(uint32_t addr, uint32_t* r) {
    asm volatile("ldmatrix.sync.aligned.m8n8.x4.shared.b16 {%0,%1,%2,%3}, [%4];"
                 : "=r"(r[0]), "=r"(r[1]), "=r"(r[2]), "=r"(r[3]) : "r"(addr));
}
__device__ __forceinline__ void ldsm4t(uint32_t addr, uint32_t* r) {
    asm volatile("ldmatrix.sync.aligned.m8n8.x4.trans.shared.b16 {%0,%1,%2,%3}, [%4];"
                 : "=r"(r[0]), "=r"(r[1]), "=r"(r[2]), "=r"(r[3]) : "r"(addr));
}
__device__ __forceinline__ void mma16816(float* c, const uint32_t* a,
                                         const uint32_t* b) {
    asm volatile(
        "mma.sync.aligned.m16n8k16.row.col.f32.f16.f16.f32 "
        "{%0,%1,%2,%3}, {%4,%5,%6,%7}, {%8,%9}, {%0,%1,%2,%3};"
        : "+f"(c[0]), "+f"(c[1]), "+f"(c[2]), "+f"(c[3])
        : "r"(a[0]), "r"(a[1]), "r"(a[2]), "r"(a[3]), "r"(b[0]), "r"(b[1]));
}

// 2-pass chunk: A hi/lo [64][64], B single [64][64] panel. (GEMM)
__device__ __forceinline__ void mma_chunk2(uint32_t aHi, uint32_t aLo,
                                           uint32_t bH, int wm, int lane,
                                           float acc[2][8][4])
{
    int rA = lane & 15;
    int cA = (lane >> 4) * 16;
#pragma unroll
    for (int ks = 0; ks < 4; ks++) {
        uint32_t ah[2][4], al[2][4], bb[4][4];
#pragma unroll
        for (int h = 0; h < 2; h++) {
            uint32_t off = swz((uint32_t)(wm * 32 + h * 16 + rA) * 128 +
                               ks * 32 + cA);
            ldsm4(aHi + off, ah[h]);
            ldsm4(aLo + off, al[h]);
        }
#pragma unroll
        for (int t = 0; t < 4; t++) {
            uint32_t off = swz((uint32_t)(ks * 16 + rA) * 128 + t * 32 + cA);
            ldsm4t(bH + off, bb[t]);
        }
#pragma unroll
        for (int h = 0; h < 2; h++)
#pragma unroll
            for (int t = 0; t < 4; t++) {
                mma16816(acc[h][2 * t], ah[h], bb[t]);
                mma16816(acc[h][2 * t + 1], ah[h], bb[t] + 2);
            }
#pragma unroll
        for (int h = 0; h < 2; h++)
#pragma unroll
            for (int t = 0; t < 4; t++) {
                mma16816(acc[h][2 * t], al[h], bb[t]);
                mma16816(acc[h][2 * t + 1], al[h], bb[t] + 2);
            }
    }
}

// 1-pass chunk: A single [64][64], B single [64][64] panel. (ATTN)
__device__ __forceinline__ void mma_chunk1(uint32_t aP, uint32_t bH,
                                           int wm, int lane,
                                           float acc[2][8][4])
{
    int rA = lane & 15;
    int cA = (lane >> 4) * 16;
#pragma unroll
    for (int ks = 0; ks < 4; ks++) {
        uint32_t ah[2][4], bb[4][4];
#pragma unroll
        for (int h = 0; h < 2; h++) {
            uint32_t off = swz((uint32_t)(wm * 32 + h * 16 + rA) * 128 +
                               ks * 32 + cA);
            ldsm4(aP + off, ah[h]);
        }
#pragma unroll
        for (int t = 0; t < 4; t++) {
            uint32_t off = swz((uint32_t)(ks * 16 + rA) * 128 + t * 32 + cA);
            ldsm4t(bH + off, bb[t]);
        }
#pragma unroll
        for (int h = 0; h < 2; h++)
#pragma unroll
            for (int t = 0; t < 4; t++) {
                mma16816(acc[h][2 * t], ah[h], bb[t]);
                mma16816(acc[h][2 * t + 1], ah[h], bb[t] + 2);
            }
    }
}

__device__ __forceinline__ void split2h(float v0, float v1, uint32_t& hw,
                                        uint32_t& lw) {
    __half2 h2 = __floats2half2_rn(v0, v1);
    float r0 = v0 - __half2float(__low2half(h2));
    float r1 = v1 - __half2float(__high2half(h2));
    __half2 l2 = __floats2half2_rn(r0, r1);
    hw = *(uint32_t*)&h2;
    lw = *(uint32_t*)&l2;
}

// ---------------- prep kernels ---------------------------------------------
__global__ void packbits_kernel(const float* __restrict__ adj,
                                uint32_t* __restrict__ bits)
{
    int row = (blockIdx.x * blockDim.x + threadIdx.x) >> 5;
    int lane = threadIdx.x & 31;
    if (row >= BB * NN) return;
    const float* ar = adj + (size_t)row * NN;
    uint32_t myword = 0;
#pragma unroll
    for (int wd = 0; wd < 32; wd++) {
        uint32_t v = __ballot_sync(0xffffffffu, ar[wd * 32 + lane] > 0.f);
        if (lane == wd) myword = v;
    }
    bits[(size_t)row * 32 + lane] = myword;
}

__global__ void split_kernel(const float* __restrict__ X,
                             fp16* __restrict__ Xh, fp16* __restrict__ Xl,
                             int n4)
{
    int i = blockIdx.x * blockDim.x + threadIdx.x;
    if (i >= n4) return;
    float4 v = *(const float4*)(X + (size_t)i * 4);
    uint2 hw, lw;
    split2h(v.x, v.y, hw.x, lw.x);
    split2h(v.z, v.w, hw.y, lw.y);
    *(uint2*)(Xh + (size_t)i * 4) = hw;
    *(uint2*)(Xl + (size_t)i * 4) = lw;
}

// ---------------- pipelined GEMM: C = A[M,K] @ B[K,256] (+bias) ------------
// 64-row tiles, 256 threads, 2 CTAs/SM. A hi/lo, B single fp16 (2-pass).
__device__ __forceinline__ void gemm_load_chunk(
    uint32_t sb, int st, int tid, int m0, int k0,
    const fp16* Ah, const fp16* Al, const fp16* Bh, int K)
{
    uint32_t s0 = sb + st * 49152;
#pragma unroll
    for (int i = tid; i < 512; i += 256) {
        int r = i >> 3, cc = i & 7;
        size_t g = (size_t)(m0 + r) * K + k0 + cc * 8;
        uint32_t so = s0 + swz(r * 128 + cc * 16);
        CP16(so, Ah + g);
        CP16(so + 8192, Al + g);
    }
#pragma unroll
    for (int i = tid; i < 2048; i += 256) {
        int r = i >> 5, c32 = i & 31;
        int p = c32 >> 3, cc = c32 & 7;
        size_t g = (size_t)(k0 + r) * 256 + c32 * 8;
        uint32_t so = s0 + 16384 + p * 8192 + swz(r * 128 + cc * 16);
        CP16(so, Bh + g);
    }
}

__global__ void __launch_bounds__(256, 2) gemm_mma_kernel(
    const fp16* __restrict__ Ah, const fp16* __restrict__ Al,
    const fp16* __restrict__ Bh, const float* __restrict__ bias,
    const float* __restrict__ a1, const float* __restrict__ a2,
    fp16* __restrict__ Chi, fp16* __restrict__ Clo, int K)
{
    extern __shared__ __align__(1024) char smem[];
    uint32_t sb = su32(smem);
    int tid = threadIdx.x, lane = tid & 31, w = tid >> 5;
    int wm = w >> 2, wn = w & 3;
    int m0 = blockIdx.x * 64;
    int nch = K >> 6;

    float acc[2][8][4];
#pragma unroll
    for (int h = 0; h < 2; h++)
#pragma unroll
        for (int t = 0; t < 8; t++)
#pragma unroll
            for (int e = 0; e < 4; e++) acc[h][t][e] = 0.f;

    gemm_load_chunk(sb, 0, tid, m0, 0, Ah, Al, Bh, K);
    CPCOMMIT();

    for (int c = 0; c < nch; c++) {
        int st = c & 1;
        CPWAIT0();
        __syncthreads();
        if (c + 1 < nch) {
            gemm_load_chunk(sb, st ^ 1, tid, m0, (c + 1) << 6, Ah, Al, Bh, K);
            CPCOMMIT();
        }
        mma_chunk2(sb + st * 49152, sb + st * 49152 + 8192,
                   sb + st * 49152 + 16384 + wn * 8192, wm, lane, acc);
    }

    // fused rowdot scratch (64 rows)
    float* s1s = (float*)(smem + 98304);
    float* s2s = s1s + 64;
    if (tid < 128) s1s[tid] = 0.f;
    __syncthreads();

    int grp = lane >> 2, qp = lane & 3;
#pragma unroll
    for (int h = 0; h < 2; h++) {
        int mA = m0 + wm * 32 + h * 16 + grp;
        float p1a = 0.f, p1b = 0.f, p2a = 0.f, p2b = 0.f;
#pragma unroll
        for (int t = 0; t < 8; t++) {
            int n = wn * 64 + t * 8 + qp * 2;
            float b0 = bias ? bias[n] : 0.f;
            float b1 = bias ? bias[n + 1] : 0.f;
            float v00 = acc[h][t][0] + b0, v01 = acc[h][t][1] + b1;
            float v10 = acc[h][t][2] + b0, v11 = acc[h][t][3] + b1;
            size_t o0 = (size_t)mA * HH + n;
            size_t o1 = (size_t)(mA + 8) * HH + n;
            uint32_t hw, lw;
            split2h(v00, v01, hw, lw);
            *(uint32_t*)(Chi + o0) = hw;
            if (Clo) *(uint32_t*)(Clo + o0) = lw;
            split2h(v10, v11, hw, lw);
            *(uint32_t*)(Chi + o1) = hw;
            if (Clo) *(uint32_t*)(Clo + o1) = lw;
            if (a1) {
                float a1v0 = a1[n], a1v1 = a1[n + 1];
                float a2v0 = a2[n], a2v1 = a2[n + 1];
                p1a += v00 * a1v0 + v01 * a1v1;
                p1b += v10 * a1v0 + v11 * a1v1;
                p2a += v00 * a2v0 + v01 * a2v1;
                p2b += v10 * a2v0 + v11 * a2v1;
            }
        }
        if (a1) {
            int lr = wm * 32 + h * 16 + grp;
            atomicAdd(&s1s[lr], p1a);
            atomicAdd(&s1s[lr + 8], p1b);
            atomicAdd(&s2s[lr], p2a);
            atomicAdd(&s2s[lr + 8], p2b);
        }
    }
    if (a1) {
        __syncthreads();
        if (tid < 64) {
            g_s1[m0 + tid] = s1s[tid];
            g_s2[m0 + tid] = s2s[tid];
        }
    }
}

// ---------------- stats + P materialization --------------------------------
// One warp per row. Each lane handles j-pairs so P stores are coalesced
// half2 (128B per warp per step). P = exp(e - m), unnormalized, fp16.
__global__ void stats_kernel(const uint32_t* __restrict__ bits,
                             fp16* __restrict__ P)
{
    int warp_in = threadIdx.x >> 5;
    int lane = threadIdx.x & 31;
    int row = blockIdx.x * 8 + warp_in;
    int b = row >> 10;
    uint32_t w = bits[(size_t)row * 32 + lane];
    const float* s2b = g_s2 + (b << 10);
    float s1v = g_s1[row];

    float e0[16], e1[16];
    float m = -INFINITY;
    int b0 = (lane & 15) * 2;
#pragma unroll
    for (int jj = 0; jj < 16; jj++) {
        int j = jj * 64 + lane * 2;
        uint32_t wj = __shfl_sync(0xffffffffu, w, jj * 2 + (lane >> 4));
        float2 s2v = *(const float2*)(s2b + j);
        float t0 = s1v + s2v.x;
        float t1 = s1v + s2v.y;
        t0 = (t0 >= 0.f) ? t0 : LALPHA * t0;
        t1 = (t1 >= 0.f) ? t1 : LALPHA * t1;
        t0 = ((wj >> b0) & 1u) ? t0 : NEGV;
        t1 = ((wj >> (b0 + 1)) & 1u) ? t1 : NEGV;
        e0[jj] = t0;
        e1[jj] = t1;
        m = fmaxf(m, fmaxf(t0, t1));
    }
#pragma unroll
    for (int off = 16; off; off >>= 1)
        m = fmaxf(m, __shfl_xor_sync(0xffffffffu, m, off));

    float l = 0.f;
    fp16* prow = P + (size_t)row * NN;
#pragma unroll
    for (int jj = 0; jj < 16; jj++) {
        float p0 = __expf(e0[jj] - m);
        float p1 = __expf(e1[jj] - m);
        l += p0 + p1;
        __half2 h2 = __floats2half2_rn(p0, p1);
        *(uint32_t*)(prow + jj * 64 + lane * 2) = *(uint32_t*)&h2;
    }
#pragma unroll
    for (int off = 16; off; off >>= 1)
        l += __shfl_xor_sync(0xffffffffu, l, off);
    if (lane == 0) g_linv[row] = 1.f / l;
}

// ---------------- pipelined attention (pure load->MMA, 2 CTAs/SM) ----------
// smem: P stages 2x8192 @0 | H stages 2x32768 @16384 | pool @81920 (2 KB).
__device__ __forceinline__ void attn_load_chunk(
    uint32_t sb, int st, int tid, int b, int i0, int j0,
    const fp16* P, const fp16* Hh)
{
    // P tile 64x64
    uint32_t p0 = sb + st * 8192;
#pragma unroll
    for (int i = tid; i < 512; i += 256) {
        int r = i >> 3, cc = i & 7;
        size_t g = (size_t)(b * NN + i0 + r) * NN + j0 + cc * 8;
        CP16(p0 + swz(r * 128 + cc * 16), P + g);
    }
    // H tile 64x256 (4 panels)
    uint32_t h0 = sb + 16384 + st * 32768;
#pragma unroll
    for (int i = tid; i < 2048; i += 256) {
        int r = i >> 5, c32 = i & 31;
        int p = c32 >> 3, cc = c32 & 7;
        size_t g = (size_t)(b * NN + j0 + r) * 256 + c32 * 8;
        CP16(h0 + p * 8192 + swz(r * 128 + cc * 16), Hh + g);
    }
}

__global__ void __launch_bounds__(256, 2) attn_mma_kernel(
    const fp16* __restrict__ P, const fp16* __restrict__ Hh,
    float* __restrict__ outF, fp16* __restrict__ Ohi, fp16* __restrict__ Olo)
{
    extern __shared__ __align__(1024) char smem[];
    uint32_t sb = su32(smem);
    int tid = threadIdx.x, lane = tid & 31, w = tid >> 5;
    int wm = w >> 2, wn = w & 3;
    int b = blockIdx.x >> 4;
    int i0 = (blockIdx.x & 15) << 6;

    attn_load_chunk(sb, 0, tid, b, i0, 0, P, Hh);
    CPCOMMIT();

    float acc[2][8][4];
#pragma unroll
    for (int h = 0; h < 2; h++)
#pragma unroll
        for (int t = 0; t < 8; t++)
#pragma unroll
            for (int e = 0; e < 4; e++) acc[h][t][e] = 0.f;

    for (int c = 0; c < 16; c++) {
        int st = c & 1;
        CPWAIT0();
        __syncthreads();
        if (c < 15) {
            attn_load_chunk(sb, st ^ 1, tid, b, i0, (c + 1) << 6, P, Hh);
            CPCOMMIT();
        }
        mma_chunk1(sb + st * 8192,
                   sb + 16384 + st * 32768 + wn * 8192, wm, lane, acc);
    }

    // pooled-reduction scratch
    float* colsum = (float*)(smem + 81920);
    float* colmax = colsum + 256;
    if (outF) {
        __syncthreads();
        if (tid < 256) { colsum[tid] = 0.f; colmax[tid] = 0.f; }
        __syncthreads();
    }

    int grp = lane >> 2, qp = lane & 3;
    float cs[8][2], cm[8][2];
#pragma unroll
    for (int t = 0; t < 8; t++) { cs[t][0] = cs[t][1] = cm[t][0] = cm[t][1] = 0.f; }

#pragma unroll
    for (int h = 0; h < 2; h++) {
        int mloc = i0 + wm * 32 + h * 16 + grp;
        float li0 = g_linv[b * NN + mloc];
        float li1 = g_linv[b * NN + mloc + 8];
        size_t rb0 = (size_t)(b * NN + mloc) * HH;
        size_t rb1 = (size_t)(b * NN + mloc + 8) * HH;
#pragma unroll
        for (int t = 0; t < 8; t++) {
            int n = wn * 64 + t * 8 + qp * 2;
            float v00 = fmaxf(acc[h][t][0] * li0, 0.f);
            float v01 = fmaxf(acc[h][t][1] * li0, 0.f);
            float v10 = fmaxf(acc[h][t][2] * li1, 0.f);
            float v11 = fmaxf(acc[h][t][3] * li1, 0.f);
            if (outF) {
                float2 f0 = {v00, v01}, f1 = {v10, v11};
                *(float2*)(outF + rb0 + n) = f0;
                *(float2*)(outF + rb1 + n) = f1;
                cs[t][0] += v00 + v10;
                cs[t][1] += v01 + v11;
                cm[t][0] = fmaxf(cm[t][0], fmaxf(v00, v10));
                cm[t][1] = fmaxf(cm[t][1], fmaxf(v01, v11));
            }
            if (Ohi) {
                uint32_t hw, lw;
                split2h(v00, v01, hw, lw);
                *(uint32_t*)(Ohi + rb0 + n) = hw;
                *(uint32_t*)(Olo + rb0 + n) = lw;
                split2h(v10, v11, hw, lw);
                *(uint32_t*)(Ohi + rb1 + n) = hw;
                *(uint32_t*)(Olo + rb1 + n) = lw;
            }
        }
    }
    if (outF) {
#pragma unroll
        for (int t = 0; t < 8; t++) {
            int n = wn * 64 + t * 8 + qp * 2;
            atomicAdd(&colsum[n], cs[t][0]);
            atomicAdd(&colsum[n + 1], cs[t][1]);
            atomicMax((int*)&colmax[n], __float_as_int(cm[t][0]));
            atomicMax((int*)&colmax[n + 1], __float_as_int(cm[t][1]));
        }
        __syncthreads();
        if (tid < 256) {
            atomicAdd(&g_sum[b * HH + tid], colsum[tid]);
            atomicMax((int*)&g_max[b * HH + tid], __float_as_int(colmax[tid]));
        }
    }
}

// ---------------- pooling init + MLP ---------------------------------------
__global__ void zero_pool_kernel()
{
    int i = blockIdx.x * blockDim.x + threadIdx.x;
    if (i < BB * HH) { g_sum[i] = 0.f; g_max[i] = 0.f; }
}

__global__ void mlp_kernel(const float* __restrict__ W1,
                           const float* __restrict__ b1,
                           const float* __restrict__ W2,
                           const float* __restrict__ b2,
                           float* __restrict__ gout)
{
    __shared__ float p[HH];
    __shared__ float y1[HH];
    int b = blockIdx.x, t = threadIdx.x;
    p[t] = g_sum[b * HH + t] * (1.f / (float)NN) + g_max[b * HH + t];
    __syncthreads();
    float acc = b1[t];
#pragma unroll 4
    for (int k = 0; k < HH; k++)
        acc = fmaf(p[k], W1[(size_t)k * HH + t], acc);
    y1[t] = fmaxf(acc, 0.f);
    __syncthreads();
    float acc2 = b2[t];
#pragma unroll 4
    for (int k = 0; k < HH; k++)
        acc2 = fmaf(y1[k], W2[(size_t)k * HH + t], acc2);
    gout[b * HH + t] = acc2;
}

// ---------------- launch ---------------------------------------------------
extern "C" void kernel_launch(void* const* d_in, const int* in_sizes, int n_in,
                              void* d_out, int out_size)
{
    const float* nf   = (const float*)d_in[0];
    const float* adj  = (const float*)d_in[1];
    const float* embW = (const float*)d_in[2];
    const float* embb = (const float*)d_in[3];
    const float* W0   = (const float*)d_in[4];
    const float* a10  = (const float*)d_in[5];
    const float* a20  = (const float*)d_in[6];
    const float* W1   = (const float*)d_in[7];
    const float* a11  = (const float*)d_in[8];
    const float* a21  = (const float*)d_in[9];
    const float* gW1  = (const float*)d_in[10];
    const float* gb1  = (const float*)d_in[11];
    const float* gW2  = (const float*)d_in[12];
    const float* gb2  = (const float*)d_in[13];

    float* outx = (float*)d_out;
    float* outg = outx + (size_t)BB * NN * HH;

    fp16 *ahi, *alo, *chi, *clo, *bhi, *whi, *wlo, *pp;
    uint32_t* bitsp;
    cudaGetSymbolAddress((void**)&ahi, g_ahi);
    cudaGetSymbolAddress((void**)&alo, g_alo);
    cudaGetSymbolAddress((void**)&chi, g_chi);
    cudaGetSymbolAddress((void**)&clo, g_clo);
    cudaGetSymbolAddress((void**)&bhi, g_bhi);
    cudaGetSymbolAddress((void**)&whi, g_whi);
    cudaGetSymbolAddress((void**)&wlo, g_wlo);
    cudaGetSymbolAddress((void**)&pp, g_p);
    cudaGetSymbolAddress((void**)&bitsp, g_adjbits);

    const int SM_G = 2 * 49152 + 1024;      // 99328  (2 CTAs/SM)
    const int SM_A = 81920 + 2048;          // 83968  (2 CTAs/SM)
    cudaFuncSetAttribute(gemm_mma_kernel,
                         cudaFuncAttributeMaxDynamicSharedMemorySize, SM_G);
    cudaFuncSetAttribute(attn_mma_kernel,
                         cudaFuncAttributeMaxDynamicSharedMemorySize, SM_A);

    const int M = BB * NN;

    packbits_kernel<<<M / 8, 256>>>(adj, bitsp);

    // ---- embed: x = nf @ embW + embb ----
    split_kernel<<<(M * FIN / 4 + 255) / 256, 256>>>(nf, ahi, alo, M * FIN / 4);
    split_kernel<<<(FIN * HH / 4 + 255) / 256, 256>>>(embW, whi, wlo,
                                                      FIN * HH / 4);
    gemm_mma_kernel<<<M / 64, 256, SM_G>>>(ahi, alo, whi, embb,
                                           nullptr, nullptr, chi, clo, FIN);

    // ---- GAT layer 0 ----
    split_kernel<<<(HH * HH / 4 + 255) / 256, 256>>>(W0, whi, wlo, HH * HH / 4);
    gemm_mma_kernel<<<M / 64, 256, SM_G>>>(chi, clo, whi, nullptr,
                                           a10, a20, bhi, nullptr, HH);
    stats_kernel<<<M / 8, 256>>>(bitsp, pp);
    attn_mma_kernel<<<BB * 16, 256, SM_A>>>(pp, bhi, nullptr, ahi, alo);

    // ---- GAT layer 1 (pool fused into attn epilogue) ----
    zero_pool_kernel<<<(BB * HH + 255) / 256, 256>>>();
    split_kernel<<<(HH * HH / 4 + 255) / 256, 256>>>(W1, whi, wlo, HH * HH / 4);
    gemm_mma_kernel<<<M / 64, 256, SM_G>>>(ahi, alo, whi, nullptr,
                                           a11, a21, bhi, nullptr, HH);
    stats_kernel<<<M / 8, 256>>>(bitsp, pp);
    attn_mma_kernel<<<BB * 16, 256, SM_A>>>(pp, bhi, outx, nullptr, nullptr);

    // ---- MLP ----
    mlp_kernel<<<BB, 256>>>(gW1, gb1, gW2, gb2, outg);
}

// round 16
// speedup vs baseline: 1.6632x; 1.0099x over previous
#include <cuda_runtime.h>
#include <cuda_fp16.h>
#include <math.h>
#include <stdint.h>

#define BB 16
#define NN 1024
#define FIN 64
#define HH 256
#define NEGV (-9e15f)
#define LALPHA 0.2f

typedef __half fp16;

// ---------------- scratch (device globals: no allocation allowed) ----------
__device__ __align__(256) fp16 g_ahi[BB * NN * HH];
__device__ __align__(256) fp16 g_alo[BB * NN * HH];
__device__ __align__(256) fp16 g_chi[BB * NN * HH];
__device__ __align__(256) fp16 g_clo[BB * NN * HH];
__device__ __align__(256) fp16 g_bhi[BB * NN * HH];       // h single fp16
__device__ __align__(256) fp16 g_whi[HH * HH];
__device__ __align__(256) fp16 g_wlo[HH * HH];            // written, unused
__device__ __align__(256) fp16 g_p[BB * NN * NN];         // P = exp(e-m), 32 MB
__device__ __align__(256) uint32_t g_adjbits[BB * NN * (NN / 32)];
__device__ __align__(256) float g_s1[BB * NN];
__device__ __align__(256) float g_s2[BB * NN];
__device__ __align__(256) float g_linv[BB * NN];
__device__ __align__(256) float g_sum[BB * HH];
__device__ __align__(256) float g_max[BB * HH];

// ---------------- helpers --------------------------------------------------
__device__ __forceinline__ uint32_t swz(uint32_t o) {
    return o ^ ((o >> 3) & 0x70);
}
__device__ __forceinline__ uint32_t su32(const void* p) {
    uint32_t a;
    asm("{ .reg .u64 t; cvta.to.shared.u64 t, %1; cvt.u32.u64 %0, t; }"
        : "=r"(a) : "l"(p));
    return a;
}
#define CP16(d, s)                                                            \
    asm volatile("cp.async.cg.shared.global [%0], [%1], 16;" ::"r"(d), "l"(s))
#define CPCOMMIT() asm volatile("cp.async.commit_group;" ::: "memory")
#define CPWAIT0() asm volatile("cp.async.wait_group 0;" ::: "memory")

__device__ __forceinline__ void ldsm4(uint32_t addr, uint32_t* r) {
    asm volatile("ldmatrix.sync.aligned.m8n8.x4.shared.b16 {%0,%1,%2,%3}, [%4];"
                 : "=r"(r[0]), "=r"(r[1]), "=r"(r[2]), "=r"(r[3]) : "r"(addr));
}
__device__ __forceinline__ void ldsm4t(uint32_t addr, uint32_t* r) {
    asm volatile("ldmatrix.sync.aligned.m8n8.x4.trans.shared.b16 {%0,%1,%2,%3}, [%4];"
                 : "=r"(r[0]), "=r"(r[1]), "=r"(r[2]), "=r"(r[3]) : "r"(addr));
}
__device__ __forceinline__ void mma16816(float* c, const uint32_t* a,
                                         const uint32_t* b) {
    asm volatile(
        "mma.sync.aligned.m16n8k16.row.col.f32.f16.f16.f32 "
        "{%0,%1,%2,%3}, {%4,%5,%6,%7}, {%8,%9}, {%0,%1,%2,%3};"
        : "+f"(c[0]), "+f"(c[1]), "+f"(c[2]), "+f"(c[3])
        : "r"(a[0]), "r"(a[1]), "r"(a[2]), "r"(a[3]), "r"(b[0]), "r"(b[1]));
}

// 2-pass chunk: A hi/lo [64][64], B single [64][64] panel. (GEMM)
__device__ __forceinline__ void mma_chunk2(uint32_t aHi, uint32_t aLo,
                                           uint32_t bH, int wm, int lane,
                                           float acc[2][8][4])
{
    int rA = lane & 15;
    int cA = (lane >> 4) * 16;
#pragma unroll
    for (int ks = 0; ks < 4; ks++) {
        uint32_t ah[2][4], al[2][4], bb[4][4];
#pragma unroll
        for (int h = 0; h < 2; h++) {
            uint32_t off = swz((uint32_t)(wm * 32 + h * 16 + rA) * 128 +
                               ks * 32 + cA);
            ldsm4(aHi + off, ah[h]);
            ldsm4(aLo + off, al[h]);
        }
#pragma unroll
        for (int t = 0; t < 4; t++) {
            uint32_t off = swz((uint32_t)(ks * 16 + rA) * 128 + t * 32 + cA);
            ldsm4t(bH + off, bb[t]);
        }
#pragma unroll
        for (int h = 0; h < 2; h++)
#pragma unroll
            for (int t = 0; t < 4; t++) {
                mma16816(acc[h][2 * t], ah[h], bb[t]);
                mma16816(acc[h][2 * t + 1], ah[h], bb[t] + 2);
            }
#pragma unroll
        for (int h = 0; h < 2; h++)
#pragma unroll
            for (int t = 0; t < 4; t++) {
                mma16816(acc[h][2 * t], al[h], bb[t]);
                mma16816(acc[h][2 * t + 1], al[h], bb[t] + 2);
            }
    }
}

// 1-pass chunk: A single [rows][64], B single [64][64] panel. (ATTN)
__device__ __forceinline__ void mma_chunk1(uint32_t aP, uint32_t bH,
                                           int wm, int lane,
                                           float acc[2][8][4])
{
    int rA = lane & 15;
    int cA = (lane >> 4) * 16;
#pragma unroll
    for (int ks = 0; ks < 4; ks++) {
        uint32_t ah[2][4], bb[4][4];
#pragma unroll
        for (int h = 0; h < 2; h++) {
            uint32_t off = swz((uint32_t)(wm * 32 + h * 16 + rA) * 128 +
                               ks * 32 + cA);
            ldsm4(aP + off, ah[h]);
        }
#pragma unroll
        for (int t = 0; t < 4; t++) {
            uint32_t off = swz((uint32_t)(ks * 16 + rA) * 128 + t * 32 + cA);
            ldsm4t(bH + off, bb[t]);
        }
#pragma unroll
        for (int h = 0; h < 2; h++)
#pragma unroll
            for (int t = 0; t < 4; t++) {
                mma16816(acc[h][2 * t], ah[h], bb[t]);
                mma16816(acc[h][2 * t + 1], ah[h], bb[t] + 2);
            }
    }
}

__device__ __forceinline__ void split2h(float v0, float v1, uint32_t& hw,
                                        uint32_t& lw) {
    __half2 h2 = __floats2half2_rn(v0, v1);
    float r0 = v0 - __half2float(__low2half(h2));
    float r1 = v1 - __half2float(__high2half(h2));
    __half2 l2 = __floats2half2_rn(r0, r1);
    hw = *(uint32_t*)&h2;
    lw = *(uint32_t*)&l2;
}

// ---------------- prep kernels ---------------------------------------------
__global__ void packbits_kernel(const float* __restrict__ adj,
                                uint32_t* __restrict__ bits)
{
    int row = (blockIdx.x * blockDim.x + threadIdx.x) >> 5;
    int lane = threadIdx.x & 31;
    if (row >= BB * NN) return;
    const float* ar = adj + (size_t)row * NN;
    uint32_t myword = 0;
#pragma unroll
    for (int wd = 0; wd < 32; wd++) {
        uint32_t v = __ballot_sync(0xffffffffu, ar[wd * 32 + lane] > 0.f);
        if (lane == wd) myword = v;
    }
    bits[(size_t)row * 32 + lane] = myword;
}

__global__ void split_kernel(const float* __restrict__ X,
                             fp16* __restrict__ Xh, fp16* __restrict__ Xl,
                             int n4)
{
    int i = blockIdx.x * blockDim.x + threadIdx.x;
    if (i >= n4) return;
    float4 v = *(const float4*)(X + (size_t)i * 4);
    uint2 hw, lw;
    split2h(v.x, v.y, hw.x, lw.x);
    split2h(v.z, v.w, hw.y, lw.y);
    *(uint2*)(Xh + (size_t)i * 4) = hw;
    *(uint2*)(Xl + (size_t)i * 4) = lw;
}

// ---------------- pipelined GEMM: C = A[M,K] @ B[K,256] (+bias) ------------
// 64-row tiles, 256 threads, 2 CTAs/SM. A hi/lo, B single fp16 (2-pass).
__device__ __forceinline__ void gemm_load_chunk(
    uint32_t sb, int st, int tid, int m0, int k0,
    const fp16* Ah, const fp16* Al, const fp16* Bh, int K)
{
    uint32_t s0 = sb + st * 49152;
#pragma unroll
    for (int i = tid; i < 512; i += 256) {
        int r = i >> 3, cc = i & 7;
        size_t g = (size_t)(m0 + r) * K + k0 + cc * 8;
        uint32_t so = s0 + swz(r * 128 + cc * 16);
        CP16(so, Ah + g);
        CP16(so + 8192, Al + g);
    }
#pragma unroll
    for (int i = tid; i < 2048; i += 256) {
        int r = i >> 5, c32 = i & 31;
        int p = c32 >> 3, cc = c32 & 7;
        size_t g = (size_t)(k0 + r) * 256 + c32 * 8;
        uint32_t so = s0 + 16384 + p * 8192 + swz(r * 128 + cc * 16);
        CP16(so, Bh + g);
    }
}

__global__ void __launch_bounds__(256, 2) gemm_mma_kernel(
    const fp16* __restrict__ Ah, const fp16* __restrict__ Al,
    const fp16* __restrict__ Bh, const float* __restrict__ bias,
    const float* __restrict__ a1, const float* __restrict__ a2,
    fp16* __restrict__ Chi, fp16* __restrict__ Clo, int K)
{
    extern __shared__ __align__(1024) char smem[];
    uint32_t sb = su32(smem);
    int tid = threadIdx.x, lane = tid & 31, w = tid >> 5;
    int wm = w >> 2, wn = w & 3;
    int m0 = blockIdx.x * 64;
    int nch = K >> 6;

    float acc[2][8][4];
#pragma unroll
    for (int h = 0; h < 2; h++)
#pragma unroll
        for (int t = 0; t < 8; t++)
#pragma unroll
            for (int e = 0; e < 4; e++) acc[h][t][e] = 0.f;

    gemm_load_chunk(sb, 0, tid, m0, 0, Ah, Al, Bh, K);
    CPCOMMIT();

    for (int c = 0; c < nch; c++) {
        int st = c & 1;
        CPWAIT0();
        __syncthreads();
        if (c + 1 < nch) {
            gemm_load_chunk(sb, st ^ 1, tid, m0, (c + 1) << 6, Ah, Al, Bh, K);
            CPCOMMIT();
        }
        mma_chunk2(sb + st * 49152, sb + st * 49152 + 8192,
                   sb + st * 49152 + 16384 + wn * 8192, wm, lane, acc);
    }

    // fused rowdot scratch (64 rows)
    float* s1s = (float*)(smem + 98304);
    float* s2s = s1s + 64;
    if (tid < 128) s1s[tid] = 0.f;
    __syncthreads();

    int grp = lane >> 2, qp = lane & 3;
#pragma unroll
    for (int h = 0; h < 2; h++) {
        int mA = m0 + wm * 32 + h * 16 + grp;
        float p1a = 0.f, p1b = 0.f, p2a = 0.f, p2b = 0.f;
#pragma unroll
        for (int t = 0; t < 8; t++) {
            int n = wn * 64 + t * 8 + qp * 2;
            float b0 = bias ? bias[n] : 0.f;
            float b1 = bias ? bias[n + 1] : 0.f;
            float v00 = acc[h][t][0] + b0, v01 = acc[h][t][1] + b1;
            float v10 = acc[h][t][2] + b0, v11 = acc[h][t][3] + b1;
            size_t o0 = (size_t)mA * HH + n;
            size_t o1 = (size_t)(mA + 8) * HH + n;
            uint32_t hw, lw;
            split2h(v00, v01, hw, lw);
            *(uint32_t*)(Chi + o0) = hw;
            if (Clo) *(uint32_t*)(Clo + o0) = lw;
            split2h(v10, v11, hw, lw);
            *(uint32_t*)(Chi + o1) = hw;
            if (Clo) *(uint32_t*)(Clo + o1) = lw;
            if (a1) {
                float a1v0 = a1[n], a1v1 = a1[n + 1];
                float a2v0 = a2[n], a2v1 = a2[n + 1];
                p1a += v00 * a1v0 + v01 * a1v1;
                p1b += v10 * a1v0 + v11 * a1v1;
                p2a += v00 * a2v0 + v01 * a2v1;
                p2b += v10 * a2v0 + v11 * a2v1;
            }
        }
        if (a1) {
            int lr = wm * 32 + h * 16 + grp;
            atomicAdd(&s1s[lr], p1a);
            atomicAdd(&s1s[lr + 8], p1b);
            atomicAdd(&s2s[lr], p2a);
            atomicAdd(&s2s[lr + 8], p2b);
        }
    }
    if (a1) {
        __syncthreads();
        if (tid < 64) {
            g_s1[m0 + tid] = s1s[tid];
            g_s2[m0 + tid] = s2s[tid];
        }
    }
}

// ---------------- stats + P materialization --------------------------------
__global__ void stats_kernel(const uint32_t* __restrict__ bits,
                             fp16* __restrict__ P)
{
    int warp_in = threadIdx.x >> 5;
    int lane = threadIdx.x & 31;
    int row = blockIdx.x * 8 + warp_in;
    int b = row >> 10;
    uint32_t w = bits[(size_t)row * 32 + lane];
    const float* s2b = g_s2 + (b << 10);
    float s1v = g_s1[row];

    float e0[16], e1[16];
    float m = -INFINITY;
    int b0 = (lane & 15) * 2;
#pragma unroll
    for (int jj = 0; jj < 16; jj++) {
        int j = jj * 64 + lane * 2;
        uint32_t wj = __shfl_sync(0xffffffffu, w, jj * 2 + (lane >> 4));
        float2 s2v = *(const float2*)(s2b + j);
        float t0 = s1v + s2v.x;
        float t1 = s1v + s2v.y;
        t0 = (t0 >= 0.f) ? t0 : LALPHA * t0;
        t1 = (t1 >= 0.f) ? t1 : LALPHA * t1;
        t0 = ((wj >> b0) & 1u) ? t0 : NEGV;
        t1 = ((wj >> (b0 + 1)) & 1u) ? t1 : NEGV;
        e0[jj] = t0;
        e1[jj] = t1;
        m = fmaxf(m, fmaxf(t0, t1));
    }
#pragma unroll
    for (int off = 16; off; off >>= 1)
        m = fmaxf(m, __shfl_xor_sync(0xffffffffu, m, off));

    float l = 0.f;
    fp16* prow = P + (size_t)row * NN;
#pragma unroll
    for (int jj = 0; jj < 16; jj++) {
        float p0 = __expf(e0[jj] - m);
        float p1 = __expf(e1[jj] - m);
        l += p0 + p1;
        __half2 h2 = __floats2half2_rn(p0, p1);
        *(uint32_t*)(prow + jj * 64 + lane * 2) = *(uint32_t*)&h2;
    }
#pragma unroll
    for (int off = 16; off; off >>= 1)
        l += __shfl_xor_sync(0xffffffffu, l, off);
    if (lane == 0) g_linv[row] = 1.f / l;
}

// ---------------- pipelined attention (128-row tiles, 512 thr, 1 CTA/SM) ---
// Chunk geometry matches gemm's proven MMA:overhead ratio: per chunk each
// warp issues 128 MMAs against a 48KB stage (round-15 rebalance).
// smem: P stages 2x16384 @0 | H stages 2x32768 @32768 | pool @98304 (2 KB).
__device__ __forceinline__ void attn_load_chunk(
    uint32_t sb, int st, int tid, int b, int i0, int j0,
    const fp16* P, const fp16* Hh)
{
    // P tile 128x64
    uint32_t p0 = sb + st * 16384;
#pragma unroll
    for (int i = tid; i < 1024; i += 512) {
        int r = i >> 3, cc = i & 7;
        size_t g = (size_t)(b * NN + i0 + r) * NN + j0 + cc * 8;
        CP16(p0 + swz(r * 128 + cc * 16), P + g);
    }
    // H tile 64x256 (4 panels)
    uint32_t h0 = sb + 32768 + st * 32768;
#pragma unroll
    for (int i = tid; i < 2048; i += 512) {
        int r = i >> 5, c32 = i & 31;
        int p = c32 >> 3, cc = c32 & 7;
        size_t g = (size_t)(b * NN + j0 + r) * 256 + c32 * 8;
        CP16(h0 + p * 8192 + swz(r * 128 + cc * 16), Hh + g);
    }
}

__global__ void __launch_bounds__(512, 1) attn_mma_kernel(
    const fp16* __restrict__ P, const fp16* __restrict__ Hh,
    float* __restrict__ outF, fp16* __restrict__ Ohi, fp16* __restrict__ Olo)
{
    extern __shared__ __align__(1024) char smem[];
    uint32_t sb = su32(smem);
    int tid = threadIdx.x, lane = tid & 31, w = tid >> 5;
    int wm = w >> 2, wn = w & 3;
    int b = blockIdx.x >> 3;
    int i0 = (blockIdx.x & 7) << 7;

    attn_load_chunk(sb, 0, tid, b, i0, 0, P, Hh);
    CPCOMMIT();

    float acc[2][8][4];
#pragma unroll
    for (int h = 0; h < 2; h++)
#pragma unroll
        for (int t = 0; t < 8; t++)
#pragma unroll
            for (int e = 0; e < 4; e++) acc[h][t][e] = 0.f;

    for (int c = 0; c < 16; c++) {
        int st = c & 1;
        CPWAIT0();
        __syncthreads();
        if (c < 15) {
            attn_load_chunk(sb, st ^ 1, tid, b, i0, (c + 1) << 6, P, Hh);
            CPCOMMIT();
        }
        mma_chunk1(sb + st * 16384,
                   sb + 32768 + st * 32768 + wn * 8192, wm, lane, acc);
    }

    // pooled-reduction scratch
    float* colsum = (float*)(smem + 98304);
    float* colmax = colsum + 256;
    if (outF) {
        __syncthreads();
        if (tid < 256) { colsum[tid] = 0.f; colmax[tid] = 0.f; }
        __syncthreads();
    }

    int grp = lane >> 2, qp = lane & 3;
    float cs[8][2], cm[8][2];
#pragma unroll
    for (int t = 0; t < 8; t++) { cs[t][0] = cs[t][1] = cm[t][0] = cm[t][1] = 0.f; }

#pragma unroll
    for (int h = 0; h < 2; h++) {
        int mloc = i0 + wm * 32 + h * 16 + grp;
        float li0 = g_linv[b * NN + mloc];
        float li1 = g_linv[b * NN + mloc + 8];
        size_t rb0 = (size_t)(b * NN + mloc) * HH;
        size_t rb1 = (size_t)(b * NN + mloc + 8) * HH;
#pragma unroll
        for (int t = 0; t < 8; t++) {
            int n = wn * 64 + t * 8 + qp * 2;
            float v00 = fmaxf(acc[h][t][0] * li0, 0.f);
            float v01 = fmaxf(acc[h][t][1] * li0, 0.f);
            float v10 = fmaxf(acc[h][t][2] * li1, 0.f);
            float v11 = fmaxf(acc[h][t][3] * li1, 0.f);
            if (outF) {
                float2 f0 = {v00, v01}, f1 = {v10, v11};
                *(float2*)(outF + rb0 + n) = f0;
                *(float2*)(outF + rb1 + n) = f1;
                cs[t][0] += v00 + v10;
                cs[t][1] += v01 + v11;
                cm[t][0] = fmaxf(cm[t][0], fmaxf(v00, v10));
                cm[t][1] = fmaxf(cm[t][1], fmaxf(v01, v11));
            }
            if (Ohi) {
                uint32_t hw, lw;
                split2h(v00, v01, hw, lw);
                *(uint32_t*)(Ohi + rb0 + n) = hw;
                *(uint32_t*)(Olo + rb0 + n) = lw;
                split2h(v10, v11, hw, lw);
                *(uint32_t*)(Ohi + rb1 + n) = hw;
                *(uint32_t*)(Olo + rb1 + n) = lw;
            }
        }
    }
    if (outF) {
#pragma unroll
        for (int t = 0; t < 8; t++) {
            int n = wn * 64 + t * 8 + qp * 2;
            atomicAdd(&colsum[n], cs[t][0]);
            atomicAdd(&colsum[n + 1], cs[t][1]);
            atomicMax((int*)&colmax[n], __float_as_int(cm[t][0]));
            atomicMax((int*)&colmax[n + 1], __float_as_int(cm[t][1]));
        }
        __syncthreads();
        if (tid < 256) {
            atomicAdd(&g_sum[b * HH + tid], colsum[tid]);
            atomicMax((int*)&g_max[b * HH + tid], __float_as_int(colmax[tid]));
        }
    }
}

// ---------------- pooling init + MLP ---------------------------------------
__global__ void zero_pool_kernel()
{
    int i = blockIdx.x * blockDim.x + threadIdx.x;
    if (i < BB * HH) { g_sum[i] = 0.f; g_max[i] = 0.f; }
}

__global__ void mlp_kernel(const float* __restrict__ W1,
                           const float* __restrict__ b1,
                           const float* __restrict__ W2,
                           const float* __restrict__ b2,
                           float* __restrict__ gout)
{
    __shared__ float p[HH];
    __shared__ float y1[HH];
    int b = blockIdx.x, t = threadIdx.x;
    p[t] = g_sum[b * HH + t] * (1.f / (float)NN) + g_max[b * HH + t];
    __syncthreads();
    float acc = b1[t];
#pragma unroll 4
    for (int k = 0; k < HH; k++)
        acc = fmaf(p[k], W1[(size_t)k * HH + t], acc);
    y1[t] = fmaxf(acc, 0.f);
    __syncthreads();
    float acc2 = b2[t];
#pragma unroll 4
    for (int k = 0; k < HH; k++)
        acc2 = fmaf(y1[k], W2[(size_t)k * HH + t], acc2);
    gout[b * HH + t] = acc2;
}

// ---------------- launch ---------------------------------------------------
extern "C" void kernel_launch(void* const* d_in, const int* in_sizes, int n_in,
                              void* d_out, int out_size)
{
    const float* nf   = (const float*)d_in[0];
    const float* adj  = (const float*)d_in[1];
    const float* embW = (const float*)d_in[2];
    const float* embb = (const float*)d_in[3];
    const float* W0   = (const float*)d_in[4];
    const float* a10  = (const float*)d_in[5];
    const float* a20  = (const float*)d_in[6];
    const float* W1   = (const float*)d_in[7];
    const float* a11  = (const float*)d_in[8];
    const float* a21  = (const float*)d_in[9];
    const float* gW1  = (const float*)d_in[10];
    const float* gb1  = (const float*)d_in[11];
    const float* gW2  = (const float*)d_in[12];
    const float* gb2  = (const float*)d_in[13];

    float* outx = (float*)d_out;
    float* outg = outx + (size_t)BB * NN * HH;

    fp16 *ahi, *alo, *chi, *clo, *bhi, *whi, *wlo, *pp;
    uint32_t* bitsp;
    cudaGetSymbolAddress((void**)&ahi, g_ahi);
    cudaGetSymbolAddress((void**)&alo, g_alo);
    cudaGetSymbolAddress((void**)&chi, g_chi);
    cudaGetSymbolAddress((void**)&clo, g_clo);
    cudaGetSymbolAddress((void**)&bhi, g_bhi);
    cudaGetSymbolAddress((void**)&whi, g_whi);
    cudaGetSymbolAddress((void**)&wlo, g_wlo);
    cudaGetSymbolAddress((void**)&pp, g_p);
    cudaGetSymbolAddress((void**)&bitsp, g_adjbits);

    const int SM_G = 2 * 49152 + 1024;      // 99328  (2 CTAs/SM)
    const int SM_A = 98304 + 2048;          // 100352 (1 CTA/SM, 512 thr)
    cudaFuncSetAttribute(gemm_mma_kernel,
                         cudaFuncAttributeMaxDynamicSharedMemorySize, SM_G);
    cudaFuncSetAttribute(attn_mma_kernel,
                         cudaFuncAttributeMaxDynamicSharedMemorySize, SM_A);

    const int M = BB * NN;

    packbits_kernel<<<M / 8, 256>>>(adj, bitsp);

    // ---- embed: x = nf @ embW + embb ----
    split_kernel<<<(M * FIN / 4 + 255) / 256, 256>>>(nf, ahi, alo, M * FIN / 4);
    split_kernel<<<(FIN * HH / 4 + 255) / 256, 256>>>(embW, whi, wlo,
                                                      FIN * HH / 4);
    gemm_mma_kernel<<<M / 64, 256, SM_G>>>(ahi, alo, whi, embb,
                                           nullptr, nullptr, chi, clo, FIN);

    // ---- GAT layer 0 ----
    split_kernel<<<(HH * HH / 4 + 255) / 256, 256>>>(W0, whi, wlo, HH * HH / 4);
    gemm_mma_kernel<<<M / 64, 256, SM_G>>>(chi, clo, whi, nullptr,
                                           a10, a20, bhi, nullptr, HH);
    stats_kernel<<<M / 8, 256>>>(bitsp, pp);
    attn_mma_kernel<<<BB * 8, 512, SM_A>>>(pp, bhi, nullptr, ahi, alo);

    // ---- GAT layer 1 (pool fused into attn epilogue) ----
    zero_pool_kernel<<<(BB * HH + 255) / 256, 256>>>();
    split_kernel<<<(HH * HH / 4 + 255) / 256, 256>>>(W1, whi, wlo, HH * HH / 4);
    gemm_mma_kernel<<<M / 64, 256, SM_G>>>(ahi, alo, whi, nullptr,
                                           a11, a21, bhi, nullptr, HH);
    stats_kernel<<<M / 8, 256>>>(bitsp, pp);
    attn_mma_kernel<<<BB * 8, 512, SM_A>>>(pp, bhi, outx, nullptr, nullptr);

    // ---- MLP ----
    mlp_kernel<<<BB, 256>>>(gW1, gb1, gW2, gb2, outg);
}

// round 17
// speedup vs baseline: 1.6789x; 1.0095x over previous
#include <cuda_runtime.h>
#include <cuda_fp16.h>
#include <math.h>
#include <stdint.h>

#define BB 16
#define NN 1024
#define FIN 64
#define HH 256
#define NEGV (-9e15f)
#define LALPHA 0.2f

typedef __half fp16;

// ---------------- scratch (device globals: no allocation allowed) ----------
__device__ __align__(256) fp16 g_ahi[BB * NN * HH];
__device__ __align__(256) fp16 g_alo[BB * NN * HH];
__device__ __align__(256) fp16 g_chi[BB * NN * HH];
__device__ __align__(256) fp16 g_clo[BB * NN * HH];
__device__ __align__(256) fp16 g_bhi[BB * NN * HH];       // h, TILED layout
__device__ __align__(256) fp16 g_whi[HH * HH];
__device__ __align__(256) fp16 g_wlo[HH * HH];            // written, unused
__device__ __align__(256) fp16 g_p[BB * NN * NN];         // P, TILED layout
__device__ __align__(256) uint32_t g_adjbits[BB * NN * (NN / 32)];
__device__ __align__(256) float g_s1[BB * NN];
__device__ __align__(256) float g_s2[BB * NN];
__device__ __align__(256) float g_linv[BB * NN];
__device__ __align__(256) float g_sum[BB * HH];
__device__ __align__(256) float g_max[BB * HH];

// ---------------- helpers --------------------------------------------------
__device__ __forceinline__ uint32_t swz(uint32_t o) {
    return o ^ ((o >> 3) & 0x70);
}
__device__ __forceinline__ uint32_t su32(const void* p) {
    uint32_t a;
    asm("{ .reg .u64 t; cvta.to.shared.u64 t, %1; cvt.u32.u64 %0, t; }"
        : "=r"(a) : "l"(p));
    return a;
}
#define CP16(d, s)                                                            \
    asm volatile("cp.async.cg.shared.global [%0], [%1], 16;" ::"r"(d), "l"(s))
#define CPCOMMIT() asm volatile("cp.async.commit_group;" ::: "memory")
#define CPWAIT0() asm volatile("cp.async.wait_group 0;" ::: "memory")

__device__ __forceinline__ void mbar_init(uint32_t mbar, uint32_t cnt) {
    asm volatile("mbarrier.init.shared.b64 [%0], %1;" :: "r"(mbar), "r"(cnt)
                 : "memory");
}
__device__ __forceinline__ void mbar_wait(uint32_t mbar, uint32_t parity) {
    asm volatile(
        "{\n\t.reg .pred P1;\n"
        "W%=:\n\t"
        "mbarrier.try_wait.parity.shared.b64 P1, [%0], %1;\n\t"
        "@P1 bra D%=;\n\t"
        "bra W%=;\n"
        "D%=:\n\t}" :: "r"(mbar), "r"(parity) : "memory");
}

__device__ __forceinline__ void ldsm4(uint32_t addr, uint32_t* r) {
    asm volatile("ldmatrix.sync.aligned.m8n8.x4.shared.b16 {%0,%1,%2,%3}, [%4];"
                 : "=r"(r[0]), "=r"(r[1]), "=r"(r[2]), "=r"(r[3]) : "r"(addr));
}
__device__ __forceinline__ void ldsm4t(uint32_t addr, uint32_t* r) {
    asm volatile("ldmatrix.sync.aligned.m8n8.x4.trans.shared.b16 {%0,%1,%2,%3}, [%4];"
                 : "=r"(r[0]), "=r"(r[1]), "=r"(r[2]), "=r"(r[3]) : "r"(addr));
}
__device__ __forceinline__ void mma16816(float* c, const uint32_t* a,
                                         const uint32_t* b) {
    asm volatile(
        "mma.sync.aligned.m16n8k16.row.col.f32.f16.f16.f32 "
        "{%0,%1,%2,%3}, {%4,%5,%6,%7}, {%8,%9}, {%0,%1,%2,%3};"
        : "+f"(c[0]), "+f"(c[1]), "+f"(c[2]), "+f"(c[3])
        : "r"(a[0]), "r"(a[1]), "r"(a[2]), "r"(a[3]), "r"(b[0]), "r"(b[1]));
}

// 2-pass chunk: A hi/lo [64][64], B single [64][64] panel. (GEMM)
__device__ __forceinline__ void mma_chunk2(uint32_t aHi, uint32_t aLo,
                                           uint32_t bH, int wm, int lane,
                                           float acc[2][8][4])
{
    int rA = lane & 15;
    int cA = (lane >> 4) * 16;
#pragma unroll
    for (int ks = 0; ks < 4; ks++) {
        uint32_t ah[2][4], al[2][4], bb[4][4];
#pragma unroll
        for (int h = 0; h < 2; h++) {
            uint32_t off = swz((uint32_t)(wm * 32 + h * 16 + rA) * 128 +
                               ks * 32 + cA);
            ldsm4(aHi + off, ah[h]);
            ldsm4(aLo + off, al[h]);
        }
#pragma unroll
        for (int t = 0; t < 4; t++) {
            uint32_t off = swz((uint32_t)(ks * 16 + rA) * 128 + t * 32 + cA);
            ldsm4t(bH + off, bb[t]);
        }
#pragma unroll
        for (int h = 0; h < 2; h++)
#pragma unroll
            for (int t = 0; t < 4; t++) {
                mma16816(acc[h][2 * t], ah[h], bb[t]);
                mma16816(acc[h][2 * t + 1], ah[h], bb[t] + 2);
            }
#pragma unroll
        for (int h = 0; h < 2; h++)
#pragma unroll
            for (int t = 0; t < 4; t++) {
                mma16816(acc[h][2 * t], al[h], bb[t]);
                mma16816(acc[h][2 * t + 1], al[h], bb[t] + 2);
            }
    }
}

// 1-pass chunk: A single [rows][64], B single [64][64] panel. (ATTN)
__device__ __forceinline__ void mma_chunk1(uint32_t aP, uint32_t bH,
                                           int wm, int lane,
                                           float acc[2][8][4])
{
    int rA = lane & 15;
    int cA = (lane >> 4) * 16;
#pragma unroll
    for (int ks = 0; ks < 4; ks++) {
        uint32_t ah[2][4], bb[4][4];
#pragma unroll
        for (int h = 0; h < 2; h++) {
            uint32_t off = swz((uint32_t)(wm * 32 + h * 16 + rA) * 128 +
                               ks * 32 + cA);
            ldsm4(aP + off, ah[h]);
        }
#pragma unroll
        for (int t = 0; t < 4; t++) {
            uint32_t off = swz((uint32_t)(ks * 16 + rA) * 128 + t * 32 + cA);
            ldsm4t(bH + off, bb[t]);
        }
#pragma unroll
        for (int h = 0; h < 2; h++)
#pragma unroll
            for (int t = 0; t < 4; t++) {
                mma16816(acc[h][2 * t], ah[h], bb[t]);
                mma16816(acc[h][2 * t + 1], ah[h], bb[t] + 2);
            }
    }
}

__device__ __forceinline__ void split2h(float v0, float v1, uint32_t& hw,
                                        uint32_t& lw) {
    __half2 h2 = __floats2half2_rn(v0, v1);
    float r0 = v0 - __half2float(__low2half(h2));
    float r1 = v1 - __half2float(__high2half(h2));
    __half2 l2 = __floats2half2_rn(r0, r1);
    hw = *(uint32_t*)&h2;
    lw = *(uint32_t*)&l2;
}

// ---------------- prep kernels ---------------------------------------------
__global__ void packbits_kernel(const float* __restrict__ adj,
                                uint32_t* __restrict__ bits)
{
    int row = (blockIdx.x * blockDim.x + threadIdx.x) >> 5;
    int lane = threadIdx.x & 31;
    if (row >= BB * NN) return;
    const float* ar = adj + (size_t)row * NN;
    uint32_t myword = 0;
#pragma unroll
    for (int wd = 0; wd < 32; wd++) {
        uint32_t v = __ballot_sync(0xffffffffu, ar[wd * 32 + lane] > 0.f);
        if (lane == wd) myword = v;
    }
    bits[(size_t)row * 32 + lane] = myword;
}

__global__ void split_kernel(const float* __restrict__ X,
                             fp16* __restrict__ Xh, fp16* __restrict__ Xl,
                             int n4)
{
    int i = blockIdx.x * blockDim.x + threadIdx.x;
    if (i >= n4) return;
    float4 v = *(const float4*)(X + (size_t)i * 4);
    uint2 hw, lw;
    split2h(v.x, v.y, hw.x, lw.x);
    split2h(v.z, v.w, hw.y, lw.y);
    *(uint2*)(Xh + (size_t)i * 4) = hw;
    *(uint2*)(Xl + (size_t)i * 4) = lw;
}

// ---------------- pipelined GEMM: C = A[M,K] @ B[K,256] (+bias) ------------
// 64-row tiles, 256 threads, 2 CTAs/SM. A hi/lo, B single fp16 (2-pass).
// htile=1: write Chi in the pre-swizzled attn tile layout
// [j>>6][n>>6 panel][j&63][64 elems xor ((j&7)<<3)].
__device__ __forceinline__ void gemm_load_chunk(
    uint32_t sb, int st, int tid, int m0, int k0,
    const fp16* Ah, const fp16* Al, const fp16* Bh, int K)
{
    uint32_t s0 = sb + st * 49152;
#pragma unroll
    for (int i = tid; i < 512; i += 256) {
        int r = i >> 3, cc = i & 7;
        size_t g = (size_t)(m0 + r) * K + k0 + cc * 8;
        uint32_t so = s0 + swz(r * 128 + cc * 16);
        CP16(so, Ah + g);
        CP16(so + 8192, Al + g);
    }
#pragma unroll
    for (int i = tid; i < 2048; i += 256) {
        int r = i >> 5, c32 = i & 31;
        int p = c32 >> 3, cc = c32 & 7;
        size_t g = (size_t)(k0 + r) * 256 + c32 * 8;
        uint32_t so = s0 + 16384 + p * 8192 + swz(r * 128 + cc * 16);
        CP16(so, Bh + g);
    }
}

__global__ void __launch_bounds__(256, 2) gemm_mma_kernel(
    const fp16* __restrict__ Ah, const fp16* __restrict__ Al,
    const fp16* __restrict__ Bh, const float* __restrict__ bias,
    const float* __restrict__ a1, const float* __restrict__ a2,
    fp16* __restrict__ Chi, fp16* __restrict__ Clo, int K, int htile)
{
    extern __shared__ __align__(1024) char smem[];
    uint32_t sb = su32(smem);
    int tid = threadIdx.x, lane = tid & 31, w = tid >> 5;
    int wm = w >> 2, wn = w & 3;
    int m0 = blockIdx.x * 64;
    int nch = K >> 6;

    float acc[2][8][4];
#pragma unroll
    for (int h = 0; h < 2; h++)
#pragma unroll
        for (int t = 0; t < 8; t++)
#pragma unroll
            for (int e = 0; e < 4; e++) acc[h][t][e] = 0.f;

    gemm_load_chunk(sb, 0, tid, m0, 0, Ah, Al, Bh, K);
    CPCOMMIT();

    for (int c = 0; c < nch; c++) {
        int st = c & 1;
        CPWAIT0();
        __syncthreads();
        if (c + 1 < nch) {
            gemm_load_chunk(sb, st ^ 1, tid, m0, (c + 1) << 6, Ah, Al, Bh, K);
            CPCOMMIT();
        }
        mma_chunk2(sb + st * 49152, sb + st * 49152 + 8192,
                   sb + st * 49152 + 16384 + wn * 8192, wm, lane, acc);
    }

    // fused rowdot scratch (64 rows)
    float* s1s = (float*)(smem + 98304);
    float* s2s = s1s + 64;
    if (tid < 128) s1s[tid] = 0.f;
    __syncthreads();

    int grp = lane >> 2, qp = lane & 3;
#pragma unroll
    for (int h = 0; h < 2; h++) {
        int mA = m0 + wm * 32 + h * 16 + grp;
        float p1a = 0.f, p1b = 0.f, p2a = 0.f, p2b = 0.f;
#pragma unroll
        for (int t = 0; t < 8; t++) {
            int n = wn * 64 + t * 8 + qp * 2;
            float b0 = bias ? bias[n] : 0.f;
            float b1 = bias ? bias[n + 1] : 0.f;
            float v00 = acc[h][t][0] + b0, v01 = acc[h][t][1] + b1;
            float v10 = acc[h][t][2] + b0, v11 = acc[h][t][3] + b1;
            uint32_t hw, lw;
            if (htile) {
                int nl = n & 63;
                uint32_t xm = (uint32_t)((mA & 7) << 3);   // same for mA+8
                size_t o0 = ((size_t)(mA >> 6) * 16384) + (size_t)wn * 4096 +
                            (size_t)(mA & 63) * 64 + (nl ^ xm);
                size_t o1 = o0 + 8 * 64;                    // (mA+8), same blk
                split2h(v00, v01, hw, lw);
                *(uint32_t*)(Chi + o0) = hw;
                split2h(v10, v11, hw, lw);
                *(uint32_t*)(Chi + o1) = hw;
            } else {
                size_t o0 = (size_t)mA * HH + n;
                size_t o1 = (size_t)(mA + 8) * HH + n;
                split2h(v00, v01, hw, lw);
                *(uint32_t*)(Chi + o0) = hw;
                if (Clo) *(uint32_t*)(Clo + o0) = lw;
                split2h(v10, v11, hw, lw);
                *(uint32_t*)(Chi + o1) = hw;
                if (Clo) *(uint32_t*)(Clo + o1) = lw;
            }
            if (a1) {
                float a1v0 = a1[n], a1v1 = a1[n + 1];
                float a2v0 = a2[n], a2v1 = a2[n + 1];
                p1a += v00 * a1v0 + v01 * a1v1;
                p1b += v10 * a1v0 + v11 * a1v1;
                p2a += v00 * a2v0 + v01 * a2v1;
                p2b += v10 * a2v0 + v11 * a2v1;
            }
        }
        if (a1) {
            int lr = wm * 32 + h * 16 + grp;
            atomicAdd(&s1s[lr], p1a);
            atomicAdd(&s1s[lr + 8], p1b);
            atomicAdd(&s2s[lr], p2a);
            atomicAdd(&s2s[lr + 8], p2b);
        }
    }
    if (a1) {
        __syncthreads();
        if (tid < 64) {
            g_s1[m0 + tid] = s1s[tid];
            g_s2[m0 + tid] = s2s[tid];
        }
    }
}

// ---------------- stats + P materialization (TILED layout) -----------------
// P layout: [(b*16+jc)*1024 + i][64 elems, col ^ ((i&7)<<3)] — exactly the
// SW128 smem tile image, so attn can cp.async.bulk it without re-swizzling.
__global__ void stats_kernel(const uint32_t* __restrict__ bits,
                             fp16* __restrict__ P)
{
    int warp_in = threadIdx.x >> 5;
    int lane = threadIdx.x & 31;
    int row = blockIdx.x * 8 + warp_in;
    int b = row >> 10;
    int il = row & 1023;
    uint32_t w = bits[(size_t)row * 32 + lane];
    const float* s2b = g_s2 + (b << 10);
    float s1v = g_s1[row];

    float e0[16], e1[16];
    float m = -INFINITY;
    int b0 = (lane & 15) * 2;
#pragma unroll
    for (int jj = 0; jj < 16; jj++) {
        int j = jj * 64 + lane * 2;
        uint32_t wj = __shfl_sync(0xffffffffu, w, jj * 2 + (lane >> 4));
        float2 s2v = *(const float2*)(s2b + j);
        float t0 = s1v + s2v.x;
        float t1 = s1v + s2v.y;
        t0 = (t0 >= 0.f) ? t0 : LALPHA * t0;
        t1 = (t1 >= 0.f) ? t1 : LALPHA * t1;
        t0 = ((wj >> b0) & 1u) ? t0 : NEGV;
        t1 = ((wj >> (b0 + 1)) & 1u) ? t1 : NEGV;
        e0[jj] = t0;
        e1[jj] = t1;
        m = fmaxf(m, fmaxf(t0, t1));
    }
#pragma unroll
    for (int off = 16; off; off >>= 1)
        m = fmaxf(m, __shfl_xor_sync(0xffffffffu, m, off));

    float l = 0.f;
    uint32_t xm = (uint32_t)((il & 7) << 3);
    uint32_t celem = ((uint32_t)(lane * 2)) ^ xm;
#pragma unroll
    for (int jj = 0; jj < 16; jj++) {
        float p0 = __expf(e0[jj] - m);
        float p1 = __expf(e1[jj] - m);
        l += p0 + p1;
        __half2 h2 = __floats2half2_rn(p0, p1);
        fp16* dst = P + (((size_t)(b * 16 + jj) * 1024 + il) * 64) + celem;
        *(uint32_t*)dst = *(uint32_t*)&h2;
    }
#pragma unroll
    for (int off = 16; off; off >>= 1)
        l += __shfl_xor_sync(0xffffffffu, l, off);
    if (lane == 0) g_linv[row] = 1.f / l;
}

// ---------------- attention: bulk-copy pipeline (128 rows, 512 thr) --------
// smem: P stages 2x16384 @0 | H stages 2x32768 @32768 | mbar @98304 |
//       pool @98432 (2 KB).
__device__ __forceinline__ void attn_issue_chunk(
    uint32_t sb, int st, uint32_t mbar, int b, int i0, int jc,
    const fp16* P, const fp16* Hh)
{
    asm volatile("mbarrier.arrive.expect_tx.shared.b64 _, [%0], %1;"
                 :: "r"(mbar), "r"(49152u) : "memory");
    const char* psrc =
        (const char*)(P + ((size_t)(b * 16 + jc) * 1024 + i0) * 64);
    asm volatile(
        "cp.async.bulk.shared::cluster.global.mbarrier::complete_tx::bytes "
        "[%0], [%1], %2, [%3];"
        :: "r"(sb + st * 16384), "l"(psrc), "r"(16384u), "r"(mbar) : "memory");
    const char* hsrc = (const char*)(Hh + (size_t)(b * 16 + jc) * 16384);
    asm volatile(
        "cp.async.bulk.shared::cluster.global.mbarrier::complete_tx::bytes "
        "[%0], [%1], %2, [%3];"
        :: "r"(sb + 32768 + st * 32768), "l"(hsrc), "r"(32768u), "r"(mbar)
        : "memory");
}

__global__ void __launch_bounds__(512, 1) attn_mma_kernel(
    const fp16* __restrict__ P, const fp16* __restrict__ Hh,
    float* __restrict__ outF, fp16* __restrict__ Ohi, fp16* __restrict__ Olo)
{
    extern __shared__ __align__(1024) char smem[];
    uint32_t sb = su32(smem);
    int tid = threadIdx.x, lane = tid & 31, w = tid >> 5;
    int wm = w >> 2, wn = w & 3;
    int b = blockIdx.x >> 3;
    int i0 = (blockIdx.x & 7) << 7;

    uint32_t mb[2] = {sb + 98304, sb + 98320};
    if (tid == 0) {
        mbar_init(mb[0], 1);
        mbar_init(mb[1], 1);
        asm volatile("fence.proxy.async.shared::cta;" ::: "memory");
    }
    __syncthreads();

    if (tid == 0) attn_issue_chunk(sb, 0, mb[0], b, i0, 0, P, Hh);

    float acc[2][8][4];
#pragma unroll
    for (int h = 0; h < 2; h++)
#pragma unroll
        for (int t = 0; t < 8; t++)
#pragma unroll
            for (int e = 0; e < 4; e++) acc[h][t][e] = 0.f;

    for (int c = 0; c < 16; c++) {
        int st = c & 1;
        mbar_wait(mb[st], (uint32_t)((c >> 1) & 1));
        __syncthreads();   // all threads done with prior mma on stage st^1
        if (c < 15 && tid == 0)
            attn_issue_chunk(sb, st ^ 1, mb[st ^ 1], b, i0, c + 1, P, Hh);
        mma_chunk1(sb + st * 16384,
                   sb + 32768 + st * 32768 + wn * 8192, wm, lane, acc);
    }

    // pooled-reduction scratch
    float* colsum = (float*)(smem + 98432);
    float* colmax = colsum + 256;
    if (outF) {
        __syncthreads();
        if (tid < 256) { colsum[tid] = 0.f; colmax[tid] = 0.f; }
        __syncthreads();
    }

    int grp = lane >> 2, qp = lane & 3;
    float cs[8][2], cm[8][2];
#pragma unroll
    for (int t = 0; t < 8; t++) { cs[t][0] = cs[t][1] = cm[t][0] = cm[t][1] = 0.f; }

#pragma unroll
    for (int h = 0; h < 2; h++) {
        int mloc = i0 + wm * 32 + h * 16 + grp;
        float li0 = g_linv[b * NN + mloc];
        float li1 = g_linv[b * NN + mloc + 8];
        size_t rb0 = (size_t)(b * NN + mloc) * HH;
        size_t rb1 = (size_t)(b * NN + mloc + 8) * HH;
#pragma unroll
        for (int t = 0; t < 8; t++) {
            int n = wn * 64 + t * 8 + qp * 2;
            float v00 = fmaxf(acc[h][t][0] * li0, 0.f);
            float v01 = fmaxf(acc[h][t][1] * li0, 0.f);
            float v10 = fmaxf(acc[h][t][2] * li1, 0.f);
            float v11 = fmaxf(acc[h][t][3] * li1, 0.f);
            if (outF) {
                float2 f0 = {v00, v01}, f1 = {v10, v11};
                *(float2*)(outF + rb0 + n) = f0;
                *(float2*)(outF + rb1 + n) = f1;
                cs[t][0] += v00 + v10;
                cs[t][1] += v01 + v11;
                cm[t][0] = fmaxf(cm[t][0], fmaxf(v00, v10));
                cm[t][1] = fmaxf(cm[t][1], fmaxf(v01, v11));
            }
            if (Ohi) {
                uint32_t hw, lw;
                split2h(v00, v01, hw, lw);
                *(uint32_t*)(Ohi + rb0 + n) = hw;
                *(uint32_t*)(Olo + rb0 + n) = lw;
                split2h(v10, v11, hw, lw);
                *(uint32_t*)(Ohi + rb1 + n) = hw;
                *(uint32_t*)(Olo + rb1 + n) = lw;
            }
        }
    }
    if (outF) {
#pragma unroll
        for (int t = 0; t < 8; t++) {
            int n = wn * 64 + t * 8 + qp * 2;
            atomicAdd(&colsum[n], cs[t][0]);
            atomicAdd(&colsum[n + 1], cs[t][1]);
            atomicMax((int*)&colmax[n], __float_as_int(cm[t][0]));
            atomicMax((int*)&colmax[n + 1], __float_as_int(cm[t][1]));
        }
        __syncthreads();
        if (tid < 256) {
            atomicAdd(&g_sum[b * HH + tid], colsum[tid]);
            atomicMax((int*)&g_max[b * HH + tid], __float_as_int(colmax[tid]));
        }
    }
}

// ---------------- pooling init + MLP ---------------------------------------
__global__ void zero_pool_kernel()
{
    int i = blockIdx.x * blockDim.x + threadIdx.x;
    if (i < BB * HH) { g_sum[i] = 0.f; g_max[i] = 0.f; }
}

__global__ void mlp_kernel(const float* __restrict__ W1,
                           const float* __restrict__ b1,
                           const float* __restrict__ W2,
                           const float* __restrict__ b2,
                           float* __restrict__ gout)
{
    __shared__ float p[HH];
    __shared__ float y1[HH];
    int b = blockIdx.x, t = threadIdx.x;
    p[t] = g_sum[b * HH + t] * (1.f / (float)NN) + g_max[b * HH + t];
    __syncthreads();
    float acc = b1[t];
#pragma unroll 4
    for (int k = 0; k < HH; k++)
        acc = fmaf(p[k], W1[(size_t)k * HH + t], acc);
    y1[t] = fmaxf(acc, 0.f);
    __syncthreads();
    float acc2 = b2[t];
#pragma unroll 4
    for (int k = 0; k < HH; k++)
        acc2 = fmaf(y1[k], W2[(size_t)k * HH + t], acc2);
    gout[b * HH + t] = acc2;
}

// ---------------- launch ---------------------------------------------------
extern "C" void kernel_launch(void* const* d_in, const int* in_sizes, int n_in,
                              void* d_out, int out_size)
{
    const float* nf   = (const float*)d_in[0];
    const float* adj  = (const float*)d_in[1];
    const float* embW = (const float*)d_in[2];
    const float* embb = (const float*)d_in[3];
    const float* W0   = (const float*)d_in[4];
    const float* a10  = (const float*)d_in[5];
    const float* a20  = (const float*)d_in[6];
    const float* W1   = (const float*)d_in[7];
    const float* a11  = (const float*)d_in[8];
    const float* a21  = (const float*)d_in[9];
    const float* gW1  = (const float*)d_in[10];
    const float* gb1  = (const float*)d_in[11];
    const float* gW2  = (const float*)d_in[12];
    const float* gb2  = (const float*)d_in[13];

    float* outx = (float*)d_out;
    float* outg = outx + (size_t)BB * NN * HH;

    fp16 *ahi, *alo, *chi, *clo, *bhi, *whi, *wlo, *pp;
    uint32_t* bitsp;
    cudaGetSymbolAddress((void**)&ahi, g_ahi);
    cudaGetSymbolAddress((void**)&alo, g_alo);
    cudaGetSymbolAddress((void**)&chi, g_chi);
    cudaGetSymbolAddress((void**)&clo, g_clo);
    cudaGetSymbolAddress((void**)&bhi, g_bhi);
    cudaGetSymbolAddress((void**)&whi, g_whi);
    cudaGetSymbolAddress((void**)&wlo, g_wlo);
    cudaGetSymbolAddress((void**)&pp, g_p);
    cudaGetSymbolAddress((void**)&bitsp, g_adjbits);

    const int SM_G = 2 * 49152 + 1024;      // 99328  (2 CTAs/SM)
    const int SM_A = 98304 + 128 + 2048;    // 100480 (1 CTA/SM, 512 thr)
    cudaFuncSetAttribute(gemm_mma_kernel,
                         cudaFuncAttributeMaxDynamicSharedMemorySize, SM_G);
    cudaFuncSetAttribute(attn_mma_kernel,
                         cudaFuncAttributeMaxDynamicSharedMemorySize, SM_A);

    const int M = BB * NN;

    packbits_kernel<<<M / 8, 256>>>(adj, bitsp);

    // ---- embed: x = nf @ embW + embb ----
    split_kernel<<<(M * FIN / 4 + 255) / 256, 256>>>(nf, ahi, alo, M * FIN / 4);
    split_kernel<<<(FIN * HH / 4 + 255) / 256, 256>>>(embW, whi, wlo,
                                                      FIN * HH / 4);
    gemm_mma_kernel<<<M / 64, 256, SM_G>>>(ahi, alo, whi, embb,
                                           nullptr, nullptr, chi, clo, FIN, 0);

    // ---- GAT layer 0 ----
    split_kernel<<<(HH * HH / 4 + 255) / 256, 256>>>(W0, whi, wlo, HH * HH / 4);
    gemm_mma_kernel<<<M / 64, 256, SM_G>>>(chi, clo, whi, nullptr,
                                           a10, a20, bhi, nullptr, HH, 1);
    stats_kernel<<<M / 8, 256>>>(bitsp, pp);
    attn_mma_kernel<<<BB * 8, 512, SM_A>>>(pp, bhi, nullptr, ahi, alo);

    // ---- GAT layer 1 (pool fused into attn epilogue) ----
    zero_pool_kernel<<<(BB * HH + 255) / 256, 256>>>();
    split_kernel<<<(HH * HH / 4 + 255) / 256, 256>>>(W1, whi, wlo, HH * HH / 4);
    gemm_mma_kernel<<<M / 64, 256, SM_G>>>(ahi, alo, whi, nullptr,
                                           a11, a21, bhi, nullptr, HH, 1);
    stats_kernel<<<M / 8, 256>>>(bitsp, pp);
    attn_mma_kernel<<<BB * 8, 512, SM_A>>>(pp, bhi, outx, nullptr, nullptr);

    // ---- MLP ----
    mlp_kernel<<<BB, 256>>>(gW1, gb1, gW2, gb2, outg);
}